// round 1
// baseline (speedup 1.0000x reference)
#include <cuda_runtime.h>
#include <cuda_bf16.h>
#include <cstdint>

// Problem constants
#define BATCH 2
#define SEQ   2048
#define FDIM  1024
#define NHEAD 16
#define HDIM  64
#define THREEF (3 * FDIM)     // 3072
#define MROWS (BATCH * SEQ)   // 4096

// Scratch (allocation-free rule: __device__ globals)
__device__ float g_qkv[(size_t)MROWS * THREEF];   // [B*S, 3F]
__device__ float g_att[(size_t)MROWS * FDIM];     // [B*S, F] pre-projection

// ---------------------------------------------------------------------------
// SGEMM (NT): C[m,n] = sum_k A[m,k] * W[n,k] + bias[n]
// A: [M,K] row-major, W: [N,K] row-major. 128x128 tile, BK=8, 256 threads,
// 8x8 per thread in 4+4 split fragments (<=2-way smem conflicts).
// M,N multiples of 128; K multiple of 8.
// ---------------------------------------------------------------------------
__global__ __launch_bounds__(256) void sgemm_nt_bias(
    const float* __restrict__ A, const float* __restrict__ W,
    const float* __restrict__ bias, float* __restrict__ C,
    int M, int N, int K)
{
    __shared__ float As[8][128];
    __shared__ float Bs[8][128];

    const int tid = threadIdx.x;
    const int m0 = blockIdx.y * 128;
    const int n0 = blockIdx.x * 128;

    const int lrow = tid >> 1;          // 0..127
    const int lk   = (tid & 1) * 4;     // 0 or 4
    const float* Aptr = A + (size_t)(m0 + lrow) * K + lk;
    const float* Wptr = W + (size_t)(n0 + lrow) * K + lk;

    const int ty = tid >> 4;            // 0..15
    const int tx = tid & 15;            // 0..15

    float acc[8][8];
    #pragma unroll
    for (int i = 0; i < 8; i++)
        #pragma unroll
        for (int j = 0; j < 8; j++) acc[i][j] = 0.f;

    for (int k0 = 0; k0 < K; k0 += 8) {
        float4 av = *(const float4*)(Aptr + k0);
        float4 bv = *(const float4*)(Wptr + k0);
        As[lk + 0][lrow] = av.x; As[lk + 1][lrow] = av.y;
        As[lk + 2][lrow] = av.z; As[lk + 3][lrow] = av.w;
        Bs[lk + 0][lrow] = bv.x; Bs[lk + 1][lrow] = bv.y;
        Bs[lk + 2][lrow] = bv.z; Bs[lk + 3][lrow] = bv.w;
        __syncthreads();

        #pragma unroll
        for (int kk = 0; kk < 8; kk++) {
            float a[8], b[8];
            *(float4*)&a[0] = *(const float4*)&As[kk][ty * 4];
            *(float4*)&a[4] = *(const float4*)&As[kk][64 + ty * 4];
            *(float4*)&b[0] = *(const float4*)&Bs[kk][tx * 4];
            *(float4*)&b[4] = *(const float4*)&Bs[kk][64 + tx * 4];
            #pragma unroll
            for (int i = 0; i < 8; i++)
                #pragma unroll
                for (int j = 0; j < 8; j++)
                    acc[i][j] = fmaf(a[i], b[j], acc[i][j]);
        }
        __syncthreads();
    }

    // Epilogue: rows {ty*4+i, 64+ty*4+i}, cols {tx*4+j, 64+tx*4+j}
    #pragma unroll
    for (int half_i = 0; half_i < 2; half_i++) {
        #pragma unroll
        for (int ii = 0; ii < 4; ii++) {
            int i = half_i * 4 + ii;
            int row = m0 + half_i * 64 + ty * 4 + ii;
            #pragma unroll
            for (int half_j = 0; half_j < 2; half_j++) {
                int colbase = n0 + half_j * 64 + tx * 4;
                float4 o;
                o.x = acc[i][half_j * 4 + 0] + bias[colbase + 0];
                o.y = acc[i][half_j * 4 + 1] + bias[colbase + 1];
                o.z = acc[i][half_j * 4 + 2] + bias[colbase + 2];
                o.w = acc[i][half_j * 4 + 3] + bias[colbase + 3];
                *(float4*)&C[(size_t)row * N + colbase] = o;
            }
        }
    }
}

// ---------------------------------------------------------------------------
// Flash attention (causal + padding). Grid: (S/64, B*H), 256 threads.
// Tiles of 64 queries x 64 keys. Per thread:
//   rows  r0..r0+3      (r0 = (tid>>4)*4)
//   score k-cols c+16j  (c = tid&15, j=0..3)  [strided -> low conflicts]
//   out   d-cols c*4..c*4+3
// Smem arrays [64][68] (stride 68 keeps float4 alignment, <=2-way conflicts).
// ---------------------------------------------------------------------------
#define PAD 68
#define ATTN_SMEM (4 * 64 * PAD * 4)   // 69632 bytes

__global__ __launch_bounds__(256) void attn_kernel(
    const float* __restrict__ qkv, const unsigned char* __restrict__ pmask,
    float* __restrict__ att)
{
    extern __shared__ float smem[];
    float* Qs = smem;
    float* Ks = smem + 64 * PAD;
    float* Vs = smem + 2 * 64 * PAD;
    float* Pt = smem + 3 * 64 * PAD;   // transposed P: Pt[kc][r]

    const int qt = blockIdx.x;
    const int bh = blockIdx.y;
    const int b = bh / NHEAD, h = bh % NHEAD;
    const int tid = threadIdx.x;
    const int rg = tid >> 4;      // 0..15
    const int c  = tid & 15;      // 0..15
    const int r0 = rg * 4;
    const int qbase = qt * 64;
    const float scale = 0.125f;   // 1/sqrt(64)

    const float* qg = qkv + (size_t)b * SEQ * THREEF + h * HDIM;
    const float* kg = qg + FDIM;
    const float* vg = qg + 2 * FDIM;

    // Load Q tile
    {
        int row = tid >> 2, part = tid & 3;
        const float* src = qg + (size_t)(qbase + row) * THREEF + part * 16;
        float* dst = &Qs[row * PAD + part * 16];
        #pragma unroll
        for (int i = 0; i < 4; i++)
            ((float4*)dst)[i] = ((const float4*)src)[i];
    }

    float m_[4], l_[4], acc[4][4];
    #pragma unroll
    for (int i = 0; i < 4; i++) {
        m_[i] = -1e30f; l_[i] = 0.f;
        #pragma unroll
        for (int j = 0; j < 4; j++) acc[i][j] = 0.f;
    }

    for (int kt = 0; kt <= qt; kt++) {
        const int kb = kt * 64;
        __syncthreads();   // prior iter done reading Ks/Vs/Pt (also covers Q load on iter 0... Q loaded pre-loop)
        // Load K and V tiles
        {
            int row = tid >> 2, part = tid & 3;
            const float* ksrc = kg + (size_t)(kb + row) * THREEF + part * 16;
            const float* vsrc = vg + (size_t)(kb + row) * THREEF + part * 16;
            float* kdst = &Ks[row * PAD + part * 16];
            float* vdst = &Vs[row * PAD + part * 16];
            #pragma unroll
            for (int i = 0; i < 4; i++) {
                ((float4*)kdst)[i] = ((const float4*)ksrc)[i];
                ((float4*)vdst)[i] = ((const float4*)vsrc)[i];
            }
        }
        __syncthreads();

        // Scores: sc[i][j] = Q[r0+i] . K[c+16j]
        float sc[4][4];
        #pragma unroll
        for (int i = 0; i < 4; i++)
            #pragma unroll
            for (int j = 0; j < 4; j++) sc[i][j] = 0.f;

        #pragma unroll
        for (int d4 = 0; d4 < 16; d4++) {
            float4 qv[4], kv[4];
            #pragma unroll
            for (int i = 0; i < 4; i++)
                qv[i] = *(const float4*)&Qs[(r0 + i) * PAD + d4 * 4];
            #pragma unroll
            for (int j = 0; j < 4; j++)
                kv[j] = *(const float4*)&Ks[(c + 16 * j) * PAD + d4 * 4];
            #pragma unroll
            for (int i = 0; i < 4; i++)
                #pragma unroll
                for (int j = 0; j < 4; j++) {
                    sc[i][j] = fmaf(qv[i].x, kv[j].x, sc[i][j]);
                    sc[i][j] = fmaf(qv[i].y, kv[j].y, sc[i][j]);
                    sc[i][j] = fmaf(qv[i].z, kv[j].z, sc[i][j]);
                    sc[i][j] = fmaf(qv[i].w, kv[j].w, sc[i][j]);
                }
        }

        // Mask + scale
        unsigned char pm[4];
        #pragma unroll
        for (int j = 0; j < 4; j++)
            pm[j] = pmask[(size_t)b * SEQ + kb + c + 16 * j];
        #pragma unroll
        for (int i = 0; i < 4; i++) {
            int qi = qbase + r0 + i;
            #pragma unroll
            for (int j = 0; j < 4; j++) {
                int ki = kb + c + 16 * j;
                float v = sc[i][j] * scale;
                if (ki > qi || pm[j]) v = -1e30f;
                sc[i][j] = v;
            }
        }

        // Online softmax update (per row i; reduce across 16 c-lanes)
        #pragma unroll
        for (int i = 0; i < 4; i++) {
            float rmax = fmaxf(fmaxf(sc[i][0], sc[i][1]), fmaxf(sc[i][2], sc[i][3]));
            #pragma unroll
            for (int off = 1; off < 16; off <<= 1)
                rmax = fmaxf(rmax, __shfl_xor_sync(0xffffffffu, rmax, off));
            float mn = fmaxf(m_[i], rmax);
            float alpha = __expf(m_[i] - mn);
            float rsum = 0.f;
            #pragma unroll
            for (int j = 0; j < 4; j++) {
                float p = __expf(sc[i][j] - mn);
                sc[i][j] = p;
                rsum += p;
            }
            #pragma unroll
            for (int off = 1; off < 16; off <<= 1)
                rsum += __shfl_xor_sync(0xffffffffu, rsum, off);
            l_[i] = l_[i] * alpha + rsum;
            m_[i] = mn;
            #pragma unroll
            for (int j = 0; j < 4; j++) acc[i][j] *= alpha;
        }

        // Write P transposed: Pt[kc][r]
        #pragma unroll
        for (int j = 0; j < 4; j++)
            #pragma unroll
            for (int i = 0; i < 4; i++)
                Pt[(c + 16 * j) * PAD + r0 + i] = sc[i][j];
        __syncthreads();

        // acc[i][jd] += sum_kc Pt[kc][r0+i] * Vs[kc][c*4+jd]
        #pragma unroll 4
        for (int kc = 0; kc < 64; kc++) {
            float4 p4 = *(const float4*)&Pt[kc * PAD + r0];
            float4 vv = *(const float4*)&Vs[kc * PAD + (c << 2)];
            acc[0][0] = fmaf(p4.x, vv.x, acc[0][0]);
            acc[0][1] = fmaf(p4.x, vv.y, acc[0][1]);
            acc[0][2] = fmaf(p4.x, vv.z, acc[0][2]);
            acc[0][3] = fmaf(p4.x, vv.w, acc[0][3]);
            acc[1][0] = fmaf(p4.y, vv.x, acc[1][0]);
            acc[1][1] = fmaf(p4.y, vv.y, acc[1][1]);
            acc[1][2] = fmaf(p4.y, vv.z, acc[1][2]);
            acc[1][3] = fmaf(p4.y, vv.w, acc[1][3]);
            acc[2][0] = fmaf(p4.z, vv.x, acc[2][0]);
            acc[2][1] = fmaf(p4.z, vv.y, acc[2][1]);
            acc[2][2] = fmaf(p4.z, vv.z, acc[2][2]);
            acc[2][3] = fmaf(p4.z, vv.w, acc[2][3]);
            acc[3][0] = fmaf(p4.w, vv.x, acc[3][0]);
            acc[3][1] = fmaf(p4.w, vv.y, acc[3][1]);
            acc[3][2] = fmaf(p4.w, vv.z, acc[3][2]);
            acc[3][3] = fmaf(p4.w, vv.w, acc[3][3]);
        }
    }

    // Normalize and write [B*S, F] at head slice
    #pragma unroll
    for (int i = 0; i < 4; i++) {
        float inv = 1.f / l_[i];
        float4 o;
        o.x = acc[i][0] * inv;
        o.y = acc[i][1] * inv;
        o.z = acc[i][2] * inv;
        o.w = acc[i][3] * inv;
        size_t row = (size_t)b * SEQ + qbase + r0 + i;
        *(float4*)&att[row * FDIM + h * HDIM + (c << 2)] = o;
    }
}

// ---------------------------------------------------------------------------
// Launch
// ---------------------------------------------------------------------------
extern "C" void kernel_launch(void* const* d_in, const int* in_sizes, int n_in,
                              void* d_out, int out_size)
{
    (void)in_sizes; (void)n_in; (void)out_size;
    const float* x      = (const float*)d_in[0];
    const unsigned char* pmask = (const unsigned char*)d_in[1];
    const float* qkv_w  = (const float*)d_in[2];
    const float* qkv_b  = (const float*)d_in[3];
    const float* out_w  = (const float*)d_in[4];
    const float* out_b  = (const float*)d_in[5];
    float* out = (float*)d_out;

    float* qkv = nullptr;
    float* att = nullptr;
    cudaGetSymbolAddress((void**)&qkv, g_qkv);
    cudaGetSymbolAddress((void**)&att, g_att);

    cudaFuncSetAttribute(attn_kernel,
                         cudaFuncAttributeMaxDynamicSharedMemorySize, ATTN_SMEM);

    // 1) QKV projection: [4096,1024] x [3072,1024]^T -> [4096,3072]
    sgemm_nt_bias<<<dim3(THREEF / 128, MROWS / 128), 256>>>(
        x, qkv_w, qkv_b, qkv, MROWS, THREEF, FDIM);

    // 2) Attention: grid (S/64, B*H)
    attn_kernel<<<dim3(SEQ / 64, BATCH * NHEAD), 256, ATTN_SMEM>>>(
        qkv, pmask, att);

    // 3) Output projection: [4096,1024] x [1024,1024]^T -> [4096,1024]
    sgemm_nt_bias<<<dim3(FDIM / 128, MROWS / 128), 256>>>(
        att, out_w, out_b, out, MROWS, FDIM, FDIM);
}

// round 3
// speedup vs baseline: 1.4352x; 1.4352x over previous
#include <cuda_runtime.h>
#include <cuda_bf16.h>
#include <cstdint>

// Problem constants
#define BATCH 2
#define SEQ   2048
#define FDIM  1024
#define NHEAD 16
#define HDIM  64
#define THREEF (3 * FDIM)     // 3072
#define MROWS (BATCH * SEQ)   // 4096

// ---------------------------------------------------------------------------
// Scratch (allocation-free rule: __device__ globals)
// ---------------------------------------------------------------------------
__device__ float g_qkv[(size_t)MROWS * THREEF];   // [B*S, 3F] fp32
__device__ float g_att[(size_t)MROWS * FDIM];     // [B*S, F]  fp32

__device__ __align__(256) __nv_bfloat16 g_xhi[(size_t)MROWS * FDIM];
__device__ __align__(256) __nv_bfloat16 g_xlo[(size_t)MROWS * FDIM];
__device__ __align__(256) __nv_bfloat16 g_whi[(size_t)THREEF * FDIM];
__device__ __align__(256) __nv_bfloat16 g_wlo[(size_t)THREEF * FDIM];
__device__ __align__(256) __nv_bfloat16 g_ahi[(size_t)MROWS * FDIM];
__device__ __align__(256) __nv_bfloat16 g_alo[(size_t)MROWS * FDIM];
__device__ __align__(256) __nv_bfloat16 g_owhi[(size_t)FDIM * FDIM];
__device__ __align__(256) __nv_bfloat16 g_owlo[(size_t)FDIM * FDIM];

// ---------------------------------------------------------------------------
// PTX helpers (base sm_100-compatible: cp.async, ldmatrix, mma.sync)
// ---------------------------------------------------------------------------
__device__ __forceinline__ uint32_t smem_u32(const void* p) {
    uint32_t a;
    asm("{ .reg .u64 t; cvta.to.shared.u64 t, %1; cvt.u32.u64 %0, t; }"
        : "=r"(a) : "l"(p));
    return a;
}

#define CP_ASYNC16(dst, src) \
    asm volatile("cp.async.cg.shared.global [%0], [%1], 16;" \
                 :: "r"((uint32_t)(dst)), "l"(src) : "memory")
#define CP_ASYNC_COMMIT() asm volatile("cp.async.commit_group;" ::: "memory")
#define CP_ASYNC_WAIT(n)  asm volatile("cp.async.wait_group %0;" :: "n"(n) : "memory")

#define LDSM_X4(r0, r1, r2, r3, addr) \
    asm volatile("ldmatrix.sync.aligned.m8n8.x4.shared.b16 {%0,%1,%2,%3}, [%4];" \
                 : "=r"(r0), "=r"(r1), "=r"(r2), "=r"(r3) : "r"(addr))

#define MMA_BF16(c, a, b) \
    asm volatile( \
        "mma.sync.aligned.m16n8k16.row.col.f32.bf16.bf16.f32 " \
        "{%0,%1,%2,%3}, {%4,%5,%6,%7}, {%8,%9}, {%0,%1,%2,%3};" \
        : "+f"((c)[0]), "+f"((c)[1]), "+f"((c)[2]), "+f"((c)[3]) \
        : "r"((a)[0]), "r"((a)[1]), "r"((a)[2]), "r"((a)[3]), \
          "r"((b)[0]), "r"((b)[1]))

// ---------------------------------------------------------------------------
// fp32 -> (bf16 hi, bf16 lo) split conversion
// ---------------------------------------------------------------------------
__global__ void split_bf16_kernel(const float* __restrict__ in,
                                  __nv_bfloat16* __restrict__ hi,
                                  __nv_bfloat16* __restrict__ lo, int n4)
{
    for (int i = blockIdx.x * blockDim.x + threadIdx.x; i < n4;
         i += gridDim.x * blockDim.x) {
        float4 v = ((const float4*)in)[i];
        __nv_bfloat16 hx = __float2bfloat16_rn(v.x);
        __nv_bfloat16 hy = __float2bfloat16_rn(v.y);
        __nv_bfloat16 hz = __float2bfloat16_rn(v.z);
        __nv_bfloat16 hw = __float2bfloat16_rn(v.w);
        __nv_bfloat162 h0; h0.x = hx; h0.y = hy;
        __nv_bfloat162 h1; h1.x = hz; h1.y = hw;
        __nv_bfloat162 l0, l1;
        l0.x = __float2bfloat16_rn(v.x - __bfloat162float(hx));
        l0.y = __float2bfloat16_rn(v.y - __bfloat162float(hy));
        l1.x = __float2bfloat16_rn(v.z - __bfloat162float(hz));
        l1.y = __float2bfloat16_rn(v.w - __bfloat162float(hw));
        ((__nv_bfloat162*)hi)[i * 2 + 0] = h0;
        ((__nv_bfloat162*)hi)[i * 2 + 1] = h1;
        ((__nv_bfloat162*)lo)[i * 2 + 0] = l0;
        ((__nv_bfloat162*)lo)[i * 2 + 1] = l1;
    }
}

// ---------------------------------------------------------------------------
// Split-bf16 tensor-core GEMM (NT): C[m,n] = sum_k A[m,k]*W[n,k] + bias[n]
// mma.sync m16n8k16 bf16, 128x128 CTA tile, BK=32, 3-stage cp.async pipeline.
// Accumulates Ahi*Bhi + Ahi*Blo + Alo*Bhi in fp32.
// Smem: per stage 4 tiles (Ahi,Alo,Bhi,Blo) of 128 rows x 32 bf16,
// row stride 40 bf16 (80 B) -> ldmatrix conflict-free.
// ---------------------------------------------------------------------------
#define BK 32
#define ROWSTRIDE 40                       // bf16 elems (80 bytes)
#define TILE_B (128 * ROWSTRIDE * 2)       // 10240 bytes per tile
#define STAGE_B (4 * TILE_B)               // 40960 bytes per stage
#define NSTAGE 3
#define GEMM_SMEM (NSTAGE * STAGE_B)       // 122880 bytes

__global__ __launch_bounds__(256) void gemm_mma_split(
    const __nv_bfloat16* __restrict__ Ahi, const __nv_bfloat16* __restrict__ Alo,
    const __nv_bfloat16* __restrict__ Bhi, const __nv_bfloat16* __restrict__ Blo,
    const float* __restrict__ bias, float* __restrict__ C,
    int M, int N, int K)
{
    extern __shared__ __align__(256) char smem[];
    const uint32_t sbase = smem_u32(smem);
    const int tid = threadIdx.x;
    const int wid = tid >> 5;
    const int lane = tid & 31;
    const int m0 = blockIdx.y * 128;
    const int n0 = blockIdx.x * 128;
    const int NC = K >> 5;                 // chunks of BK=32

    const int wm = (wid & 3) * 32;         // warp m offset (4 slices)
    const int wn = (wid >> 2) * 64;        // warp n offset (2 slices)

    // cp.async mapping: i = tid + j*256; tile = i>>9; rem = i&511;
    // row = rem>>2; seg = rem&3 (16B segments of the 64B row)
    auto load_stage = [&](int c, int s) {
        const int kc = c << 5;
        const uint32_t sb = sbase + (uint32_t)s * STAGE_B;
        #pragma unroll
        for (int j = 0; j < 8; j++) {
            int i = tid + j * 256;
            int tile = i >> 9;
            int rem = i & 511;
            int row = rem >> 2;
            int seg = rem & 3;
            uint32_t dst = sb + (uint32_t)tile * TILE_B
                         + (uint32_t)row * (ROWSTRIDE * 2) + (uint32_t)seg * 16;
            const __nv_bfloat16* base;
            size_t off;
            if (tile < 2) {
                base = (tile == 0) ? Ahi : Alo;
                off = (size_t)(m0 + row) * K + kc + seg * 8;
            } else {
                base = (tile == 2) ? Bhi : Blo;
                off = (size_t)(n0 + row) * K + kc + seg * 8;
            }
            CP_ASYNC16(dst, (const char*)(base + off));
        }
        CP_ASYNC_COMMIT();
    };

    float acc[2][8][4];
    #pragma unroll
    for (int i = 0; i < 2; i++)
        #pragma unroll
        for (int j = 0; j < 8; j++)
            #pragma unroll
            for (int r = 0; r < 4; r++) acc[i][j][r] = 0.f;

    // Prologue
    #pragma unroll
    for (int s = 0; s < NSTAGE; s++)
        if (s < NC) load_stage(s, s);

    // ldmatrix lane addressing
    const int a_row = lane & 15;           // rows 0..15 within m16 tile
    const int a_kh  = lane >> 4;           // k half (0/1) * 8
    const int b_q   = lane >> 3;           // quad 0..3
    const int b_i   = lane & 7;
    const int b_n   = ((b_q >> 1) * 8) + b_i;   // n within n16 group
    const int b_k   = (b_q & 1) * 8;            // k offset

    for (int c = 0; c < NC; c++) {
        if (c + 2 < NC)      CP_ASYNC_WAIT(2);
        else if (c + 1 < NC) CP_ASYNC_WAIT(1);
        else                 CP_ASYNC_WAIT(0);
        __syncthreads();

        const uint32_t sb = sbase + (uint32_t)(c % NSTAGE) * STAGE_B;
        const uint32_t sAh = sb;
        const uint32_t sAl = sb + TILE_B;
        const uint32_t sBh = sb + 2 * TILE_B;
        const uint32_t sBl = sb + 3 * TILE_B;

        #pragma unroll
        for (int ks = 0; ks < 2; ks++) {
            const uint32_t koff = (uint32_t)(ks * 32 + a_kh * 16);
            uint32_t ah[2][4], al[2][4];
            #pragma unroll
            for (int mt = 0; mt < 2; mt++) {
                uint32_t ra = (uint32_t)(wm + mt * 16 + a_row) * (ROWSTRIDE * 2) + koff;
                LDSM_X4(ah[mt][0], ah[mt][1], ah[mt][2], ah[mt][3], sAh + ra);
                LDSM_X4(al[mt][0], al[mt][1], al[mt][2], al[mt][3], sAl + ra);
            }
            const uint32_t bkoff = (uint32_t)(ks * 32 + b_k * 2);
            #pragma unroll
            for (int nh = 0; nh < 2; nh++) {
                uint32_t bh[4][2], bl[4][2];
                #pragma unroll
                for (int p = 0; p < 2; p++) {
                    uint32_t rb = (uint32_t)(wn + nh * 32 + p * 16 + b_n) * (ROWSTRIDE * 2) + bkoff;
                    LDSM_X4(bh[p * 2][0], bh[p * 2][1], bh[p * 2 + 1][0], bh[p * 2 + 1][1], sBh + rb);
                    LDSM_X4(bl[p * 2][0], bl[p * 2][1], bl[p * 2 + 1][0], bl[p * 2 + 1][1], sBl + rb);
                }
                #pragma unroll
                for (int mt = 0; mt < 2; mt++)
                    #pragma unroll
                    for (int jn = 0; jn < 4; jn++) {
                        float* cc = acc[mt][nh * 4 + jn];
                        MMA_BF16(cc, ah[mt], bh[jn]);
                        MMA_BF16(cc, ah[mt], bl[jn]);
                        MMA_BF16(cc, al[mt], bh[jn]);
                    }
            }
        }
        __syncthreads();
        if (c + NSTAGE < NC) load_stage(c + NSTAGE, (c + NSTAGE) % NSTAGE);
    }

    // Epilogue: c frag m16n8: rows g, g+8 (g = lane>>2), cols 2t, 2t+1 (t = lane&3)
    const int g = lane >> 2;
    const int t = lane & 3;
    #pragma unroll
    for (int mt = 0; mt < 2; mt++) {
        #pragma unroll
        for (int j = 0; j < 8; j++) {
            const int col = n0 + wn + j * 8 + t * 2;
            const float bx = bias[col], by = bias[col + 1];
            const int r0 = m0 + wm + mt * 16 + g;
            float2 v0 = make_float2(acc[mt][j][0] + bx, acc[mt][j][1] + by);
            float2 v1 = make_float2(acc[mt][j][2] + bx, acc[mt][j][3] + by);
            *(float2*)&C[(size_t)r0 * N + col] = v0;
            *(float2*)&C[(size_t)(r0 + 8) * N + col] = v1;
        }
    }
}

// ---------------------------------------------------------------------------
// Flash attention (causal + padding), fp32 SIMT. Grid: (S/64, B*H), 256 thr.
// ---------------------------------------------------------------------------
#define PAD 68
#define ATTN_SMEM (4 * 64 * PAD * 4)   // 69632 bytes

__global__ __launch_bounds__(256) void attn_kernel(
    const float* __restrict__ qkv, const unsigned char* __restrict__ pmask,
    float* __restrict__ att)
{
    extern __shared__ float fsmem[];
    float* Qs = fsmem;
    float* Ks = fsmem + 64 * PAD;
    float* Vs = fsmem + 2 * 64 * PAD;
    float* Pt = fsmem + 3 * 64 * PAD;

    const int qt = blockIdx.x;
    const int bh = blockIdx.y;
    const int b = bh / NHEAD, h = bh % NHEAD;
    const int tid = threadIdx.x;
    const int rg = tid >> 4;
    const int c  = tid & 15;
    const int r0 = rg * 4;
    const int qbase = qt * 64;
    const float scale = 0.125f;

    const float* qg = qkv + (size_t)b * SEQ * THREEF + h * HDIM;
    const float* kg = qg + FDIM;
    const float* vg = qg + 2 * FDIM;

    {
        int row = tid >> 2, part = tid & 3;
        const float* src = qg + (size_t)(qbase + row) * THREEF + part * 16;
        float* dst = &Qs[row * PAD + part * 16];
        #pragma unroll
        for (int i = 0; i < 4; i++)
            ((float4*)dst)[i] = ((const float4*)src)[i];
    }

    float m_[4], l_[4], acc[4][4];
    #pragma unroll
    for (int i = 0; i < 4; i++) {
        m_[i] = -1e30f; l_[i] = 0.f;
        #pragma unroll
        for (int j = 0; j < 4; j++) acc[i][j] = 0.f;
    }

    for (int kt = 0; kt <= qt; kt++) {
        const int kb = kt * 64;
        __syncthreads();
        {
            int row = tid >> 2, part = tid & 3;
            const float* ksrc = kg + (size_t)(kb + row) * THREEF + part * 16;
            const float* vsrc = vg + (size_t)(kb + row) * THREEF + part * 16;
            float* kdst = &Ks[row * PAD + part * 16];
            float* vdst = &Vs[row * PAD + part * 16];
            #pragma unroll
            for (int i = 0; i < 4; i++) {
                ((float4*)kdst)[i] = ((const float4*)ksrc)[i];
                ((float4*)vdst)[i] = ((const float4*)vsrc)[i];
            }
        }
        __syncthreads();

        float sc[4][4];
        #pragma unroll
        for (int i = 0; i < 4; i++)
            #pragma unroll
            for (int j = 0; j < 4; j++) sc[i][j] = 0.f;

        #pragma unroll
        for (int d4 = 0; d4 < 16; d4++) {
            float4 qv[4], kv[4];
            #pragma unroll
            for (int i = 0; i < 4; i++)
                qv[i] = *(const float4*)&Qs[(r0 + i) * PAD + d4 * 4];
            #pragma unroll
            for (int j = 0; j < 4; j++)
                kv[j] = *(const float4*)&Ks[(c + 16 * j) * PAD + d4 * 4];
            #pragma unroll
            for (int i = 0; i < 4; i++)
                #pragma unroll
                for (int j = 0; j < 4; j++) {
                    sc[i][j] = fmaf(qv[i].x, kv[j].x, sc[i][j]);
                    sc[i][j] = fmaf(qv[i].y, kv[j].y, sc[i][j]);
                    sc[i][j] = fmaf(qv[i].z, kv[j].z, sc[i][j]);
                    sc[i][j] = fmaf(qv[i].w, kv[j].w, sc[i][j]);
                }
        }

        unsigned char pm[4];
        #pragma unroll
        for (int j = 0; j < 4; j++)
            pm[j] = pmask[(size_t)b * SEQ + kb + c + 16 * j];
        #pragma unroll
        for (int i = 0; i < 4; i++) {
            int qi = qbase + r0 + i;
            #pragma unroll
            for (int j = 0; j < 4; j++) {
                int ki = kb + c + 16 * j;
                float v = sc[i][j] * scale;
                if (ki > qi || pm[j]) v = -1e30f;
                sc[i][j] = v;
            }
        }

        #pragma unroll
        for (int i = 0; i < 4; i++) {
            float rmax = fmaxf(fmaxf(sc[i][0], sc[i][1]), fmaxf(sc[i][2], sc[i][3]));
            #pragma unroll
            for (int off = 1; off < 16; off <<= 1)
                rmax = fmaxf(rmax, __shfl_xor_sync(0xffffffffu, rmax, off));
            float mn = fmaxf(m_[i], rmax);
            float alpha = __expf(m_[i] - mn);
            float rsum = 0.f;
            #pragma unroll
            for (int j = 0; j < 4; j++) {
                float p = __expf(sc[i][j] - mn);
                sc[i][j] = p;
                rsum += p;
            }
            #pragma unroll
            for (int off = 1; off < 16; off <<= 1)
                rsum += __shfl_xor_sync(0xffffffffu, rsum, off);
            l_[i] = l_[i] * alpha + rsum;
            m_[i] = mn;
            #pragma unroll
            for (int j = 0; j < 4; j++) acc[i][j] *= alpha;
        }

        #pragma unroll
        for (int j = 0; j < 4; j++)
            #pragma unroll
            for (int i = 0; i < 4; i++)
                Pt[(c + 16 * j) * PAD + r0 + i] = sc[i][j];
        __syncthreads();

        #pragma unroll 4
        for (int kc = 0; kc < 64; kc++) {
            float4 p4 = *(const float4*)&Pt[kc * PAD + r0];
            float4 vv = *(const float4*)&Vs[kc * PAD + (c << 2)];
            acc[0][0] = fmaf(p4.x, vv.x, acc[0][0]);
            acc[0][1] = fmaf(p4.x, vv.y, acc[0][1]);
            acc[0][2] = fmaf(p4.x, vv.z, acc[0][2]);
            acc[0][3] = fmaf(p4.x, vv.w, acc[0][3]);
            acc[1][0] = fmaf(p4.y, vv.x, acc[1][0]);
            acc[1][1] = fmaf(p4.y, vv.y, acc[1][1]);
            acc[1][2] = fmaf(p4.y, vv.z, acc[1][2]);
            acc[1][3] = fmaf(p4.y, vv.w, acc[1][3]);
            acc[2][0] = fmaf(p4.z, vv.x, acc[2][0]);
            acc[2][1] = fmaf(p4.z, vv.y, acc[2][1]);
            acc[2][2] = fmaf(p4.z, vv.z, acc[2][2]);
            acc[2][3] = fmaf(p4.z, vv.w, acc[2][3]);
            acc[3][0] = fmaf(p4.w, vv.x, acc[3][0]);
            acc[3][1] = fmaf(p4.w, vv.y, acc[3][1]);
            acc[3][2] = fmaf(p4.w, vv.z, acc[3][2]);
            acc[3][3] = fmaf(p4.w, vv.w, acc[3][3]);
        }
    }

    #pragma unroll
    for (int i = 0; i < 4; i++) {
        float inv = 1.f / l_[i];
        float4 o;
        o.x = acc[i][0] * inv;
        o.y = acc[i][1] * inv;
        o.z = acc[i][2] * inv;
        o.w = acc[i][3] * inv;
        size_t row = (size_t)b * SEQ + qbase + r0 + i;
        *(float4*)&att[row * FDIM + h * HDIM + (c << 2)] = o;
    }
}

// ---------------------------------------------------------------------------
// Launch
// ---------------------------------------------------------------------------
extern "C" void kernel_launch(void* const* d_in, const int* in_sizes, int n_in,
                              void* d_out, int out_size)
{
    (void)in_sizes; (void)n_in; (void)out_size;
    const float* x      = (const float*)d_in[0];
    const unsigned char* pmask = (const unsigned char*)d_in[1];
    const float* qkv_w  = (const float*)d_in[2];
    const float* qkv_b  = (const float*)d_in[3];
    const float* out_w  = (const float*)d_in[4];
    const float* out_b  = (const float*)d_in[5];
    float* out = (float*)d_out;

    float *qkv, *att;
    __nv_bfloat16 *xhi, *xlo, *whi, *wlo, *ahi, *alo, *owhi, *owlo;
    cudaGetSymbolAddress((void**)&qkv, g_qkv);
    cudaGetSymbolAddress((void**)&att, g_att);
    cudaGetSymbolAddress((void**)&xhi, g_xhi);
    cudaGetSymbolAddress((void**)&xlo, g_xlo);
    cudaGetSymbolAddress((void**)&whi, g_whi);
    cudaGetSymbolAddress((void**)&wlo, g_wlo);
    cudaGetSymbolAddress((void**)&ahi, g_ahi);
    cudaGetSymbolAddress((void**)&alo, g_alo);
    cudaGetSymbolAddress((void**)&owhi, g_owhi);
    cudaGetSymbolAddress((void**)&owlo, g_owlo);

    static bool attr_done = false;
    if (!attr_done) {
        cudaFuncSetAttribute(attn_kernel,
                             cudaFuncAttributeMaxDynamicSharedMemorySize, ATTN_SMEM);
        cudaFuncSetAttribute(gemm_mma_split,
                             cudaFuncAttributeMaxDynamicSharedMemorySize, GEMM_SMEM);
        attr_done = true;
    }

    // Split conversions
    split_bf16_kernel<<<512, 256>>>(x, xhi, xlo, MROWS * FDIM / 4);
    split_bf16_kernel<<<512, 256>>>(qkv_w, whi, wlo, THREEF * FDIM / 4);
    split_bf16_kernel<<<256, 256>>>(out_w, owhi, owlo, FDIM * FDIM / 4);

    // 1) QKV projection: [4096,1024] x [3072,1024]^T -> [4096,3072]
    gemm_mma_split<<<dim3(THREEF / 128, MROWS / 128), 256, GEMM_SMEM>>>(
        xhi, xlo, whi, wlo, qkv_b, qkv, MROWS, THREEF, FDIM);

    // 2) Attention
    attn_kernel<<<dim3(SEQ / 64, BATCH * NHEAD), 256, ATTN_SMEM>>>(
        qkv, pmask, att);

    // 3) Split attention output, then output projection
    split_bf16_kernel<<<512, 256>>>(att, ahi, alo, MROWS * FDIM / 4);
    gemm_mma_split<<<dim3(FDIM / 128, MROWS / 128), 256, GEMM_SMEM>>>(
        ahi, alo, owhi, owlo, out_b, out, MROWS, FDIM, FDIM);
}

// round 4
// speedup vs baseline: 2.3398x; 1.6302x over previous
#include <cuda_runtime.h>
#include <cuda_bf16.h>
#include <cstdint>

// Problem constants
#define BATCH 2
#define SEQ   2048
#define FDIM  1024
#define NHEAD 16
#define HDIM  64
#define THREEF (3 * FDIM)     // 3072
#define MROWS (BATCH * SEQ)   // 4096

// ---------------------------------------------------------------------------
// Scratch (allocation-free rule: __device__ globals)
// ---------------------------------------------------------------------------
__device__ __align__(256) __nv_bfloat16 g_xhi[(size_t)MROWS * FDIM];
__device__ __align__(256) __nv_bfloat16 g_xlo[(size_t)MROWS * FDIM];
__device__ __align__(256) __nv_bfloat16 g_whi[(size_t)THREEF * FDIM];
__device__ __align__(256) __nv_bfloat16 g_wlo[(size_t)THREEF * FDIM];
__device__ __align__(256) __nv_bfloat16 g_qkvhi[(size_t)MROWS * THREEF];
__device__ __align__(256) __nv_bfloat16 g_qkvlo[(size_t)MROWS * THREEF];
__device__ __align__(256) __nv_bfloat16 g_ahi[(size_t)MROWS * FDIM];
__device__ __align__(256) __nv_bfloat16 g_alo[(size_t)MROWS * FDIM];
__device__ __align__(256) __nv_bfloat16 g_owhi[(size_t)FDIM * FDIM];
__device__ __align__(256) __nv_bfloat16 g_owlo[(size_t)FDIM * FDIM];

// ---------------------------------------------------------------------------
// PTX helpers (base sm_100-compatible: cp.async, ldmatrix, mma.sync)
// ---------------------------------------------------------------------------
__device__ __forceinline__ uint32_t smem_u32(const void* p) {
    uint32_t a;
    asm("{ .reg .u64 t; cvta.to.shared.u64 t, %1; cvt.u32.u64 %0, t; }"
        : "=r"(a) : "l"(p));
    return a;
}

#define CP_ASYNC16(dst, src) \
    asm volatile("cp.async.cg.shared.global [%0], [%1], 16;" \
                 :: "r"((uint32_t)(dst)), "l"(src) : "memory")
#define CP_ASYNC_COMMIT() asm volatile("cp.async.commit_group;" ::: "memory")
#define CP_ASYNC_WAIT(n)  asm volatile("cp.async.wait_group %0;" :: "n"(n) : "memory")

#define LDSM_X4(r0, r1, r2, r3, addr) \
    asm volatile("ldmatrix.sync.aligned.m8n8.x4.shared.b16 {%0,%1,%2,%3}, [%4];" \
                 : "=r"(r0), "=r"(r1), "=r"(r2), "=r"(r3) : "r"(addr))

#define LDSM_X4_T(r0, r1, r2, r3, addr) \
    asm volatile("ldmatrix.sync.aligned.m8n8.x4.trans.shared.b16 {%0,%1,%2,%3}, [%4];" \
                 : "=r"(r0), "=r"(r1), "=r"(r2), "=r"(r3) : "r"(addr))

#define MMA_BF16(c, a, b) \
    asm volatile( \
        "mma.sync.aligned.m16n8k16.row.col.f32.bf16.bf16.f32 " \
        "{%0,%1,%2,%3}, {%4,%5,%6,%7}, {%8,%9}, {%0,%1,%2,%3};" \
        : "+f"((c)[0]), "+f"((c)[1]), "+f"((c)[2]), "+f"((c)[3]) \
        : "r"((a)[0]), "r"((a)[1]), "r"((a)[2]), "r"((a)[3]), \
          "r"((b)[0]), "r"((b)[1]))

__device__ __forceinline__ uint32_t pack_bf2(float a, float b) {
    __nv_bfloat162 h = __floats2bfloat162_rn(a, b);
    return *reinterpret_cast<uint32_t*>(&h);
}

// Fast 2^x for x <= 0 (FMA pipe only, no MUFU). rel err ~2.4e-6.
__device__ __forceinline__ float exp2_fast(float x) {
    float t = fmaxf(x, -120.f);
    int i = __float2int_rn(t);
    float f = t - (float)i;
    float p = 0.0013333558f;
    p = fmaf(p, f, 0.0096181291f);
    p = fmaf(p, f, 0.0555041087f);
    p = fmaf(p, f, 0.2402265069f);
    p = fmaf(p, f, 0.6931471806f);
    p = fmaf(p, f, 1.0f);
    return __int_as_float(__float_as_int(p) + (i << 23));
}

// ---------------------------------------------------------------------------
// fp32 -> (bf16 hi, bf16 lo) split conversion
// ---------------------------------------------------------------------------
__global__ void split_bf16_kernel(const float* __restrict__ in,
                                  __nv_bfloat16* __restrict__ hi,
                                  __nv_bfloat16* __restrict__ lo, int n4)
{
    for (int i = blockIdx.x * blockDim.x + threadIdx.x; i < n4;
         i += gridDim.x * blockDim.x) {
        float4 v = ((const float4*)in)[i];
        __nv_bfloat16 hx = __float2bfloat16_rn(v.x);
        __nv_bfloat16 hy = __float2bfloat16_rn(v.y);
        __nv_bfloat16 hz = __float2bfloat16_rn(v.z);
        __nv_bfloat16 hw = __float2bfloat16_rn(v.w);
        __nv_bfloat162 h0; h0.x = hx; h0.y = hy;
        __nv_bfloat162 h1; h1.x = hz; h1.y = hw;
        __nv_bfloat162 l0, l1;
        l0.x = __float2bfloat16_rn(v.x - __bfloat162float(hx));
        l0.y = __float2bfloat16_rn(v.y - __bfloat162float(hy));
        l1.x = __float2bfloat16_rn(v.z - __bfloat162float(hz));
        l1.y = __float2bfloat16_rn(v.w - __bfloat162float(hw));
        ((__nv_bfloat162*)hi)[i * 2 + 0] = h0;
        ((__nv_bfloat162*)hi)[i * 2 + 1] = h1;
        ((__nv_bfloat162*)lo)[i * 2 + 0] = l0;
        ((__nv_bfloat162*)lo)[i * 2 + 1] = l1;
    }
}

// ---------------------------------------------------------------------------
// Split-bf16 tensor-core GEMM (NT): C = A*W^T + bias
// If Cf != nullptr -> write fp32 C; else write split bf16 (Chi, Clo).
// ---------------------------------------------------------------------------
#define BK 32
#define ROWSTRIDE 40
#define TILE_B (128 * ROWSTRIDE * 2)
#define STAGE_B (4 * TILE_B)
#define NSTAGE 3
#define GEMM_SMEM (NSTAGE * STAGE_B)

__global__ __launch_bounds__(256) void gemm_mma_split(
    const __nv_bfloat16* __restrict__ Ahi, const __nv_bfloat16* __restrict__ Alo,
    const __nv_bfloat16* __restrict__ Bhi, const __nv_bfloat16* __restrict__ Blo,
    const float* __restrict__ bias, float* __restrict__ Cf,
    __nv_bfloat16* __restrict__ Chi, __nv_bfloat16* __restrict__ Clo,
    int M, int N, int K)
{
    extern __shared__ __align__(256) char smem[];
    const uint32_t sbase = smem_u32(smem);
    const int tid = threadIdx.x;
    const int wid = tid >> 5;
    const int lane = tid & 31;
    const int m0 = blockIdx.y * 128;
    const int n0 = blockIdx.x * 128;
    const int NC = K >> 5;

    const int wm = (wid & 3) * 32;
    const int wn = (wid >> 2) * 64;

    auto load_stage = [&](int c, int s) {
        const int kc = c << 5;
        const uint32_t sb = sbase + (uint32_t)s * STAGE_B;
        #pragma unroll
        for (int j = 0; j < 8; j++) {
            int i = tid + j * 256;
            int tile = i >> 9;
            int rem = i & 511;
            int row = rem >> 2;
            int seg = rem & 3;
            uint32_t dst = sb + (uint32_t)tile * TILE_B
                         + (uint32_t)row * (ROWSTRIDE * 2) + (uint32_t)seg * 16;
            const __nv_bfloat16* base;
            size_t off;
            if (tile < 2) {
                base = (tile == 0) ? Ahi : Alo;
                off = (size_t)(m0 + row) * K + kc + seg * 8;
            } else {
                base = (tile == 2) ? Bhi : Blo;
                off = (size_t)(n0 + row) * K + kc + seg * 8;
            }
            CP_ASYNC16(dst, (const char*)(base + off));
        }
        CP_ASYNC_COMMIT();
    };

    float acc[2][8][4];
    #pragma unroll
    for (int i = 0; i < 2; i++)
        #pragma unroll
        for (int j = 0; j < 8; j++)
            #pragma unroll
            for (int r = 0; r < 4; r++) acc[i][j][r] = 0.f;

    #pragma unroll
    for (int s = 0; s < NSTAGE; s++)
        if (s < NC) load_stage(s, s);

    const int a_row = lane & 15;
    const int a_kh  = lane >> 4;
    const int b_q   = lane >> 3;
    const int b_i   = lane & 7;
    const int b_n   = ((b_q >> 1) * 8) + b_i;
    const int b_k   = (b_q & 1) * 8;

    for (int c = 0; c < NC; c++) {
        if (c + 2 < NC)      CP_ASYNC_WAIT(2);
        else if (c + 1 < NC) CP_ASYNC_WAIT(1);
        else                 CP_ASYNC_WAIT(0);
        __syncthreads();

        const uint32_t sb = sbase + (uint32_t)(c % NSTAGE) * STAGE_B;
        const uint32_t sAh = sb;
        const uint32_t sAl = sb + TILE_B;
        const uint32_t sBh = sb + 2 * TILE_B;
        const uint32_t sBl = sb + 3 * TILE_B;

        #pragma unroll
        for (int ks = 0; ks < 2; ks++) {
            const uint32_t koff = (uint32_t)(ks * 32 + a_kh * 16);
            uint32_t ah[2][4], al[2][4];
            #pragma unroll
            for (int mt = 0; mt < 2; mt++) {
                uint32_t ra = (uint32_t)(wm + mt * 16 + a_row) * (ROWSTRIDE * 2) + koff;
                LDSM_X4(ah[mt][0], ah[mt][1], ah[mt][2], ah[mt][3], sAh + ra);
                LDSM_X4(al[mt][0], al[mt][1], al[mt][2], al[mt][3], sAl + ra);
            }
            const uint32_t bkoff = (uint32_t)(ks * 32 + b_k * 2);
            #pragma unroll
            for (int nh = 0; nh < 2; nh++) {
                uint32_t bh[4][2], bl[4][2];
                #pragma unroll
                for (int p = 0; p < 2; p++) {
                    uint32_t rb = (uint32_t)(wn + nh * 32 + p * 16 + b_n) * (ROWSTRIDE * 2) + bkoff;
                    LDSM_X4(bh[p * 2][0], bh[p * 2][1], bh[p * 2 + 1][0], bh[p * 2 + 1][1], sBh + rb);
                    LDSM_X4(bl[p * 2][0], bl[p * 2][1], bl[p * 2 + 1][0], bl[p * 2 + 1][1], sBl + rb);
                }
                #pragma unroll
                for (int mt = 0; mt < 2; mt++)
                    #pragma unroll
                    for (int jn = 0; jn < 4; jn++) {
                        float* cc = acc[mt][nh * 4 + jn];
                        MMA_BF16(cc, ah[mt], bh[jn]);
                        MMA_BF16(cc, ah[mt], bl[jn]);
                        MMA_BF16(cc, al[mt], bh[jn]);
                    }
            }
        }
        __syncthreads();
        if (c + NSTAGE < NC) load_stage(c + NSTAGE, (c + NSTAGE) % NSTAGE);
    }

    const int g = lane >> 2;
    const int t = lane & 3;
    #pragma unroll
    for (int mt = 0; mt < 2; mt++) {
        #pragma unroll
        for (int j = 0; j < 8; j++) {
            const int col = n0 + wn + j * 8 + t * 2;
            const float bx = bias[col], by = bias[col + 1];
            const int r0 = m0 + wm + mt * 16 + g;
            float v00 = acc[mt][j][0] + bx, v01 = acc[mt][j][1] + by;
            float v10 = acc[mt][j][2] + bx, v11 = acc[mt][j][3] + by;
            if (Cf) {
                *(float2*)&Cf[(size_t)r0 * N + col] = make_float2(v00, v01);
                *(float2*)&Cf[(size_t)(r0 + 8) * N + col] = make_float2(v10, v11);
            } else {
                __nv_bfloat16 h00 = __float2bfloat16_rn(v00);
                __nv_bfloat16 h01 = __float2bfloat16_rn(v01);
                __nv_bfloat16 h10 = __float2bfloat16_rn(v10);
                __nv_bfloat16 h11 = __float2bfloat16_rn(v11);
                *(uint32_t*)&Chi[(size_t)r0 * N + col] = pack_bf2(__bfloat162float(h00), 0.f) * 0 +
                    (*(uint32_t*)&h00 | ((uint32_t)*(uint16_t*)&h01 << 16));
                *(uint32_t*)&Chi[(size_t)(r0 + 8) * N + col] =
                    (*(uint16_t*)&h10 | ((uint32_t)*(uint16_t*)&h11 << 16));
                *(uint32_t*)&Clo[(size_t)r0 * N + col] =
                    pack_bf2(v00 - __bfloat162float(h00), v01 - __bfloat162float(h01));
                *(uint32_t*)&Clo[(size_t)(r0 + 8) * N + col] =
                    pack_bf2(v10 - __bfloat162float(h10), v11 - __bfloat162float(h11));
            }
        }
    }
}

// ---------------------------------------------------------------------------
// Flash attention on tensor cores (split bf16, causal + padding).
// Grid: (16, B*H), 256 threads = 8 warps. Q tile 128, K tile 64, D=64.
// Softmax in base-2 with FMA-pipe exp2.
// ---------------------------------------------------------------------------
#define RS 144                       // smem row stride bytes (72 bf16)
#define Q_TILE_B (128 * RS)          // 18432
#define KV_TILE_B (64 * RS)          // 9216
#define KV_STAGE_B (4 * KV_TILE_B)   // 36864
#define ATTN_SMEM (2 * Q_TILE_B + 2 * KV_STAGE_B)  // 110592
#define SCALE2 0.1803368801111243f   // 0.125 * log2(e)

__global__ __launch_bounds__(256, 1) void attn_mma(
    const __nv_bfloat16* __restrict__ qkvhi, const __nv_bfloat16* __restrict__ qkvlo,
    const unsigned char* __restrict__ pmask,
    __nv_bfloat16* __restrict__ ahi, __nv_bfloat16* __restrict__ alo)
{
    extern __shared__ __align__(256) char smem[];
    const uint32_t sbase = smem_u32(smem);
    const int qt = gridDim.x - 1 - blockIdx.x;     // big tiles first
    const int bh = blockIdx.y;
    const int b = bh >> 4, h = bh & 15;
    const int tid = threadIdx.x;
    const int wid = tid >> 5;
    const int lane = tid & 31;
    const int wm = wid * 16;
    const int qbase = qt * 128;
    const int nkt = 2 * qt + 2;

    const uint32_t sQH = sbase;
    const uint32_t sQL = sbase + Q_TILE_B;
    const uint32_t sKV = sbase + 2 * Q_TILE_B;

    const size_t rb = (size_t)b * SEQ;
    const __nv_bfloat16* qh_g = qkvhi + rb * THREEF + h * HDIM;
    const __nv_bfloat16* ql_g = qkvlo + rb * THREEF + h * HDIM;
    const __nv_bfloat16* kh_g = qh_g + FDIM;
    const __nv_bfloat16* kl_g = ql_g + FDIM;
    const __nv_bfloat16* vh_g = qh_g + 2 * FDIM;
    const __nv_bfloat16* vl_g = ql_g + 2 * FDIM;

    auto load_kv = [&](int kt_, int s_) {
        const int kb_ = kt_ * 64;
        const uint32_t sb = sKV + (uint32_t)s_ * KV_STAGE_B;
        #pragma unroll
        for (int t = 0; t < 8; t++) {
            int i = tid + t * 256;
            int tsr = i >> 9;
            int rem = i & 511;
            int row = rem >> 3, seg = rem & 7;
            const __nv_bfloat16* g =
                (tsr == 0) ? kh_g : (tsr == 1) ? kl_g : (tsr == 2) ? vh_g : vl_g;
            const char* src = (const char*)(g + (size_t)(kb_ + row) * THREEF + seg * 8);
            uint32_t dst = sb + (uint32_t)tsr * KV_TILE_B + (uint32_t)row * RS + seg * 16;
            CP_ASYNC16(dst, src);
        }
    };

    // Load Q (both tensors) + first KV stage, one commit group
    {
        #pragma unroll
        for (int t = 0; t < 8; t++) {
            int i = tid + t * 256;
            int tsr = i >> 10;
            int rem = i & 1023;
            int row = rem >> 3, seg = rem & 7;
            const __nv_bfloat16* g = tsr ? ql_g : qh_g;
            const char* src = (const char*)(g + (size_t)(qbase + row) * THREEF + seg * 8);
            uint32_t dst = (tsr ? sQL : sQH) + (uint32_t)row * RS + seg * 16;
            CP_ASYNC16(dst, src);
        }
        load_kv(0, 0);
        CP_ASYNC_COMMIT();
    }
    CP_ASYNC_WAIT(0);
    __syncthreads();

    // Q fragments held in registers for the whole loop
    const int a_row = lane & 15;
    const int a_kh  = lane >> 4;
    uint32_t qfh[4][4], qfl[4][4];
    #pragma unroll
    for (int ks = 0; ks < 4; ks++) {
        uint32_t ra = (uint32_t)(wm + a_row) * RS + ks * 32 + a_kh * 16;
        LDSM_X4(qfh[ks][0], qfh[ks][1], qfh[ks][2], qfh[ks][3], sQH + ra);
        LDSM_X4(qfl[ks][0], qfl[ks][1], qfl[ks][2], qfl[ks][3], sQL + ra);
    }

    float O[8][4];
    #pragma unroll
    for (int j = 0; j < 8; j++)
        #pragma unroll
        for (int r = 0; r < 4; r++) O[j][r] = 0.f;
    float m2[2] = {-1e30f, -1e30f};
    float l_[2] = {0.f, 0.f};

    const int b_q = lane >> 3;
    const int b_i = lane & 7;
    const int b_n = ((b_q >> 1) * 8) + b_i;
    const uint32_t b_koffB = (uint32_t)((b_q & 1) * 16);  // bytes
    const int r_lo = qbase + wm + (lane >> 2);
    const int r_hi = r_lo + 8;
    const int t2 = (lane & 3) * 2;

    for (int kt = 0; kt < nkt; kt++) {
        const int kb = kt * 64;
        const int s = kt & 1;
        if (kt + 1 < nkt) { load_kv(kt + 1, s ^ 1); CP_ASYNC_COMMIT(); }

        const uint32_t sKH = sKV + (uint32_t)s * KV_STAGE_B;
        const uint32_t sKL = sKH + KV_TILE_B;
        const uint32_t sVH = sKH + 2 * KV_TILE_B;
        const uint32_t sVL = sKH + 3 * KV_TILE_B;

        // ---- S = Q K^T (split bf16, fp32 accum) ----
        float S_[8][4];
        #pragma unroll
        for (int j = 0; j < 8; j++)
            #pragma unroll
            for (int r = 0; r < 4; r++) S_[j][r] = 0.f;

        #pragma unroll
        for (int ks = 0; ks < 4; ks++) {
            #pragma unroll
            for (int g4 = 0; g4 < 4; g4++) {
                uint32_t kh0, kh1, kh2, kh3, kl0, kl1, kl2, kl3;
                uint32_t raK = (uint32_t)(g4 * 16 + b_n) * RS + ks * 32 + b_koffB;
                LDSM_X4(kh0, kh1, kh2, kh3, sKH + raK);
                LDSM_X4(kl0, kl1, kl2, kl3, sKL + raK);
                uint32_t bh0[2] = {kh0, kh1}, bh1[2] = {kh2, kh3};
                uint32_t bl0[2] = {kl0, kl1}, bl1[2] = {kl2, kl3};
                MMA_BF16(S_[2 * g4], qfh[ks], bh0);
                MMA_BF16(S_[2 * g4], qfh[ks], bl0);
                MMA_BF16(S_[2 * g4], qfl[ks], bh0);
                MMA_BF16(S_[2 * g4 + 1], qfh[ks], bh1);
                MMA_BF16(S_[2 * g4 + 1], qfh[ks], bl1);
                MMA_BF16(S_[2 * g4 + 1], qfl[ks], bh1);
            }
        }

        // ---- mask + scale into base-2 domain ----
        #pragma unroll
        for (int j = 0; j < 8; j++) {
            const int colb = kb + j * 8 + t2;
            unsigned short pm = *(const unsigned short*)(pmask + rb + colb);
            const bool p0 = pm & 0xFF, p1 = pm >> 8;
            S_[j][0] = (p0 || colb > r_lo)     ? -1e30f : S_[j][0] * SCALE2;
            S_[j][1] = (p1 || colb + 1 > r_lo) ? -1e30f : S_[j][1] * SCALE2;
            S_[j][2] = (p0 || colb > r_hi)     ? -1e30f : S_[j][2] * SCALE2;
            S_[j][3] = (p1 || colb + 1 > r_hi) ? -1e30f : S_[j][3] * SCALE2;
        }

        // ---- online softmax (base-2) ----
        float mx0 = -1e30f, mx1 = -1e30f;
        #pragma unroll
        for (int j = 0; j < 8; j++) {
            mx0 = fmaxf(mx0, fmaxf(S_[j][0], S_[j][1]));
            mx1 = fmaxf(mx1, fmaxf(S_[j][2], S_[j][3]));
        }
        mx0 = fmaxf(mx0, __shfl_xor_sync(0xffffffffu, mx0, 1));
        mx0 = fmaxf(mx0, __shfl_xor_sync(0xffffffffu, mx0, 2));
        mx1 = fmaxf(mx1, __shfl_xor_sync(0xffffffffu, mx1, 1));
        mx1 = fmaxf(mx1, __shfl_xor_sync(0xffffffffu, mx1, 2));
        const float mn0 = fmaxf(m2[0], mx0);
        const float mn1 = fmaxf(m2[1], mx1);
        const float al0 = exp2_fast(m2[0] - mn0);
        const float al1 = exp2_fast(m2[1] - mn1);
        m2[0] = mn0; m2[1] = mn1;

        float sum0 = 0.f, sum1 = 0.f;
        #pragma unroll
        for (int j = 0; j < 8; j++) {
            S_[j][0] = exp2_fast(S_[j][0] - mn0);
            S_[j][1] = exp2_fast(S_[j][1] - mn0);
            S_[j][2] = exp2_fast(S_[j][2] - mn1);
            S_[j][3] = exp2_fast(S_[j][3] - mn1);
            sum0 += S_[j][0] + S_[j][1];
            sum1 += S_[j][2] + S_[j][3];
        }
        sum0 += __shfl_xor_sync(0xffffffffu, sum0, 1);
        sum0 += __shfl_xor_sync(0xffffffffu, sum0, 2);
        sum1 += __shfl_xor_sync(0xffffffffu, sum1, 1);
        sum1 += __shfl_xor_sync(0xffffffffu, sum1, 2);
        l_[0] = l_[0] * al0 + sum0;
        l_[1] = l_[1] * al1 + sum1;

        #pragma unroll
        for (int j = 0; j < 8; j++) {
            O[j][0] *= al0; O[j][1] *= al0;
            O[j][2] *= al1; O[j][3] *= al1;
        }

        // ---- O += P V (P split in regs, V via ldmatrix.trans, split) ----
        #pragma unroll
        for (int kk = 0; kk < 4; kk++) {
            float a00 = S_[2 * kk][0],     a01 = S_[2 * kk][1];
            float a10 = S_[2 * kk][2],     a11 = S_[2 * kk][3];
            float a20 = S_[2 * kk + 1][0], a21 = S_[2 * kk + 1][1];
            float a30 = S_[2 * kk + 1][2], a31 = S_[2 * kk + 1][3];
            uint32_t ph[4], pl[4];
            ph[0] = pack_bf2(a00, a01);
            ph[1] = pack_bf2(a10, a11);
            ph[2] = pack_bf2(a20, a21);
            ph[3] = pack_bf2(a30, a31);
            __nv_bfloat162 h;
            h = *(__nv_bfloat162*)&ph[0];
            pl[0] = pack_bf2(a00 - __bfloat162float(h.x), a01 - __bfloat162float(h.y));
            h = *(__nv_bfloat162*)&ph[1];
            pl[1] = pack_bf2(a10 - __bfloat162float(h.x), a11 - __bfloat162float(h.y));
            h = *(__nv_bfloat162*)&ph[2];
            pl[2] = pack_bf2(a20 - __bfloat162float(h.x), a21 - __bfloat162float(h.y));
            h = *(__nv_bfloat162*)&ph[3];
            pl[3] = pack_bf2(a30 - __bfloat162float(h.x), a31 - __bfloat162float(h.y));

            #pragma unroll
            for (int dp = 0; dp < 4; dp++) {
                uint32_t raV = (uint32_t)(kk * 16 + (lane & 15)) * RS
                             + (uint32_t)(dp * 32 + (lane >> 4) * 16);
                uint32_t v0, v1, v2, v3, w0, w1, w2, w3;
                LDSM_X4_T(v0, v1, v2, v3, sVH + raV);
                LDSM_X4_T(w0, w1, w2, w3, sVL + raV);
                uint32_t bh0[2] = {v0, v1}, bh1[2] = {v2, v3};
                uint32_t bl0[2] = {w0, w1}, bl1[2] = {w2, w3};
                MMA_BF16(O[dp * 2],     ph, bh0);
                MMA_BF16(O[dp * 2],     pl, bh0);
                MMA_BF16(O[dp * 2],     ph, bl0);
                MMA_BF16(O[dp * 2 + 1], ph, bh1);
                MMA_BF16(O[dp * 2 + 1], pl, bh1);
                MMA_BF16(O[dp * 2 + 1], ph, bl1);
            }
        }

        if (kt + 1 < nkt) { CP_ASYNC_WAIT(0); __syncthreads(); }
    }

    // ---- epilogue: normalize, split to bf16 hi/lo, write ----
    const float inv0 = 1.f / l_[0];
    const float inv1 = 1.f / l_[1];
    const size_t row0 = rb + (size_t)r_lo;
    const size_t row1 = rb + (size_t)r_hi;
    #pragma unroll
    for (int j = 0; j < 8; j++) {
        const int col = h * HDIM + j * 8 + t2;
        float v00 = O[j][0] * inv0, v01 = O[j][1] * inv0;
        float v10 = O[j][2] * inv1, v11 = O[j][3] * inv1;
        uint32_t h0 = pack_bf2(v00, v01);
        uint32_t h1 = pack_bf2(v10, v11);
        __nv_bfloat162 hh;
        hh = *(__nv_bfloat162*)&h0;
        uint32_t l0 = pack_bf2(v00 - __bfloat162float(hh.x), v01 - __bfloat162float(hh.y));
        hh = *(__nv_bfloat162*)&h1;
        uint32_t l1 = pack_bf2(v10 - __bfloat162float(hh.x), v11 - __bfloat162float(hh.y));
        *(uint32_t*)&ahi[row0 * FDIM + col] = h0;
        *(uint32_t*)&ahi[row1 * FDIM + col] = h1;
        *(uint32_t*)&alo[row0 * FDIM + col] = l0;
        *(uint32_t*)&alo[row1 * FDIM + col] = l1;
    }
}

// ---------------------------------------------------------------------------
// Launch
// ---------------------------------------------------------------------------
extern "C" void kernel_launch(void* const* d_in, const int* in_sizes, int n_in,
                              void* d_out, int out_size)
{
    (void)in_sizes; (void)n_in; (void)out_size;
    const float* x      = (const float*)d_in[0];
    const unsigned char* pmask = (const unsigned char*)d_in[1];
    const float* qkv_w  = (const float*)d_in[2];
    const float* qkv_b  = (const float*)d_in[3];
    const float* out_w  = (const float*)d_in[4];
    const float* out_b  = (const float*)d_in[5];
    float* out = (float*)d_out;

    __nv_bfloat16 *xhi, *xlo, *whi, *wlo, *qkvhi, *qkvlo, *ahi, *alo, *owhi, *owlo;
    cudaGetSymbolAddress((void**)&xhi, g_xhi);
    cudaGetSymbolAddress((void**)&xlo, g_xlo);
    cudaGetSymbolAddress((void**)&whi, g_whi);
    cudaGetSymbolAddress((void**)&wlo, g_wlo);
    cudaGetSymbolAddress((void**)&qkvhi, g_qkvhi);
    cudaGetSymbolAddress((void**)&qkvlo, g_qkvlo);
    cudaGetSymbolAddress((void**)&ahi, g_ahi);
    cudaGetSymbolAddress((void**)&alo, g_alo);
    cudaGetSymbolAddress((void**)&owhi, g_owhi);
    cudaGetSymbolAddress((void**)&owlo, g_owlo);

    static bool attr_done = false;
    if (!attr_done) {
        cudaFuncSetAttribute(gemm_mma_split,
                             cudaFuncAttributeMaxDynamicSharedMemorySize, GEMM_SMEM);
        cudaFuncSetAttribute(attn_mma,
                             cudaFuncAttributeMaxDynamicSharedMemorySize, ATTN_SMEM);
        attr_done = true;
    }

    // Split conversions (inputs only)
    split_bf16_kernel<<<512, 256>>>(x, xhi, xlo, MROWS * FDIM / 4);
    split_bf16_kernel<<<512, 256>>>(qkv_w, whi, wlo, THREEF * FDIM / 4);
    split_bf16_kernel<<<256, 256>>>(out_w, owhi, owlo, FDIM * FDIM / 4);

    // 1) QKV projection -> split bf16 qkv
    gemm_mma_split<<<dim3(THREEF / 128, MROWS / 128), 256, GEMM_SMEM>>>(
        xhi, xlo, whi, wlo, qkv_b, nullptr, qkvhi, qkvlo, MROWS, THREEF, FDIM);

    // 2) Attention (tensor cores) -> split bf16 att
    attn_mma<<<dim3(SEQ / 128, BATCH * NHEAD), 256, ATTN_SMEM>>>(
        qkvhi, qkvlo, pmask, ahi, alo);

    // 3) Output projection -> fp32 out
    gemm_mma_split<<<dim3(FDIM / 128, MROWS / 128), 256, GEMM_SMEM>>>(
        ahi, alo, owhi, owlo, out_b, out, nullptr, nullptr, MROWS, FDIM, FDIM);
}

// round 5
// speedup vs baseline: 2.9175x; 1.2469x over previous
#include <cuda_runtime.h>
#include <cuda_bf16.h>
#include <cstdint>

// Problem constants
#define BATCH 2
#define SEQ   2048
#define FDIM  1024
#define NHEAD 16
#define HDIM  64
#define THREEF (3 * FDIM)     // 3072
#define MROWS (BATCH * SEQ)   // 4096

// ---------------------------------------------------------------------------
// Scratch (allocation-free rule: __device__ globals)
// ---------------------------------------------------------------------------
__device__ __align__(256) __nv_bfloat16 g_xhi[(size_t)MROWS * FDIM];
__device__ __align__(256) __nv_bfloat16 g_xlo[(size_t)MROWS * FDIM];
__device__ __align__(256) __nv_bfloat16 g_whi[(size_t)THREEF * FDIM];
__device__ __align__(256) __nv_bfloat16 g_wlo[(size_t)THREEF * FDIM];
__device__ __align__(256) __nv_bfloat16 g_qkvhi[(size_t)MROWS * THREEF];
__device__ __align__(256) __nv_bfloat16 g_qkvlo[(size_t)MROWS * THREEF];
__device__ __align__(256) __nv_bfloat16 g_ahi[(size_t)MROWS * FDIM];
__device__ __align__(256) __nv_bfloat16 g_alo[(size_t)MROWS * FDIM];
__device__ __align__(256) __nv_bfloat16 g_owhi[(size_t)FDIM * FDIM];
__device__ __align__(256) __nv_bfloat16 g_owlo[(size_t)FDIM * FDIM];

// ---------------------------------------------------------------------------
// PTX helpers (base sm_100-compatible: cp.async, ldmatrix, mma.sync)
// ---------------------------------------------------------------------------
__device__ __forceinline__ uint32_t smem_u32(const void* p) {
    uint32_t a;
    asm("{ .reg .u64 t; cvta.to.shared.u64 t, %1; cvt.u32.u64 %0, t; }"
        : "=r"(a) : "l"(p));
    return a;
}

#define CP_ASYNC16(dst, src) \
    asm volatile("cp.async.cg.shared.global [%0], [%1], 16;" \
                 :: "r"((uint32_t)(dst)), "l"(src) : "memory")
#define CP_ASYNC_COMMIT() asm volatile("cp.async.commit_group;" ::: "memory")
#define CP_ASYNC_WAIT(n)  asm volatile("cp.async.wait_group %0;" :: "n"(n) : "memory")

#define LDSM_X4(r0, r1, r2, r3, addr) \
    asm volatile("ldmatrix.sync.aligned.m8n8.x4.shared.b16 {%0,%1,%2,%3}, [%4];" \
                 : "=r"(r0), "=r"(r1), "=r"(r2), "=r"(r3) : "r"(addr))

#define LDSM_X4_T(r0, r1, r2, r3, addr) \
    asm volatile("ldmatrix.sync.aligned.m8n8.x4.trans.shared.b16 {%0,%1,%2,%3}, [%4];" \
                 : "=r"(r0), "=r"(r1), "=r"(r2), "=r"(r3) : "r"(addr))

#define MMA_BF16(c, a, b) \
    asm volatile( \
        "mma.sync.aligned.m16n8k16.row.col.f32.bf16.bf16.f32 " \
        "{%0,%1,%2,%3}, {%4,%5,%6,%7}, {%8,%9}, {%0,%1,%2,%3};" \
        : "+f"((c)[0]), "+f"((c)[1]), "+f"((c)[2]), "+f"((c)[3]) \
        : "r"((a)[0]), "r"((a)[1]), "r"((a)[2]), "r"((a)[3]), \
          "r"((b)[0]), "r"((b)[1]))

__device__ __forceinline__ uint32_t pack_bf2(float a, float b) {
    __nv_bfloat162 h = __floats2bfloat162_rn(a, b);
    return *reinterpret_cast<uint32_t*>(&h);
}

// SW128 swizzle: XOR 16B-segment bits [4:6] with row bits [7:9]
#define SW128(off) ((off) ^ (((off) >> 3) & 0x70))

// Fast 2^x for x <= 0 (FMA pipe only, no MUFU). rel err ~2.4e-6.
__device__ __forceinline__ float exp2_fast(float x) {
    float t = fmaxf(x, -120.f);
    int i = __float2int_rn(t);
    float f = t - (float)i;
    float p = 0.0013333558f;
    p = fmaf(p, f, 0.0096181291f);
    p = fmaf(p, f, 0.0555041087f);
    p = fmaf(p, f, 0.2402265069f);
    p = fmaf(p, f, 0.6931471806f);
    p = fmaf(p, f, 1.0f);
    return __int_as_float(__float_as_int(p) + (i << 23));
}

// ---------------------------------------------------------------------------
// fp32 -> (bf16 hi, bf16 lo) split conversion
// ---------------------------------------------------------------------------
__global__ void split_bf16_kernel(const float* __restrict__ in,
                                  __nv_bfloat16* __restrict__ hi,
                                  __nv_bfloat16* __restrict__ lo, int n4)
{
    for (int i = blockIdx.x * blockDim.x + threadIdx.x; i < n4;
         i += gridDim.x * blockDim.x) {
        float4 v = ((const float4*)in)[i];
        __nv_bfloat16 hx = __float2bfloat16_rn(v.x);
        __nv_bfloat16 hy = __float2bfloat16_rn(v.y);
        __nv_bfloat16 hz = __float2bfloat16_rn(v.z);
        __nv_bfloat16 hw = __float2bfloat16_rn(v.w);
        __nv_bfloat162 h0; h0.x = hx; h0.y = hy;
        __nv_bfloat162 h1; h1.x = hz; h1.y = hw;
        __nv_bfloat162 l0, l1;
        l0.x = __float2bfloat16_rn(v.x - __bfloat162float(hx));
        l0.y = __float2bfloat16_rn(v.y - __bfloat162float(hy));
        l1.x = __float2bfloat16_rn(v.z - __bfloat162float(hz));
        l1.y = __float2bfloat16_rn(v.w - __bfloat162float(hw));
        ((__nv_bfloat162*)hi)[i * 2 + 0] = h0;
        ((__nv_bfloat162*)hi)[i * 2 + 1] = h1;
        ((__nv_bfloat162*)lo)[i * 2 + 0] = l0;
        ((__nv_bfloat162*)lo)[i * 2 + 1] = l1;
    }
}

// ---------------------------------------------------------------------------
// Split-bf16 tensor-core GEMM (NT): C = A*W^T + bias
// CTA tile 256(M) x 128(N), BK=64, warp tile 64x64 (8 warps, 4x2).
// Smem: unpadded 128B rows + SW128 swizzle; 2-stage cp.async pipeline.
// If Cf != nullptr -> write fp32 C; else write split bf16 (Chi, Clo).
// ---------------------------------------------------------------------------
#define A_TILE_B2 (256 * 128)                     // 32768 per tensor
#define B_TILE_B2 (128 * 128)                     // 16384 per tensor
#define STAGE2_B (2 * A_TILE_B2 + 2 * B_TILE_B2)  // 98304
#define GEMM_SMEM (2 * STAGE2_B)                  // 196608

__global__ __launch_bounds__(256, 1) void gemm_mma_split(
    const __nv_bfloat16* __restrict__ Ahi, const __nv_bfloat16* __restrict__ Alo,
    const __nv_bfloat16* __restrict__ Bhi, const __nv_bfloat16* __restrict__ Blo,
    const float* __restrict__ bias, float* __restrict__ Cf,
    __nv_bfloat16* __restrict__ Chi, __nv_bfloat16* __restrict__ Clo,
    int M, int N, int K)
{
    extern __shared__ __align__(256) char smem[];
    const uint32_t sbase = smem_u32(smem);
    const int tid = threadIdx.x;
    const int wid = tid >> 5;
    const int lane = tid & 31;
    const int m0 = blockIdx.y * 256;
    const int n0 = blockIdx.x * 128;
    const int NC = K >> 6;                 // chunks of 64

    const int wm = (wid & 3) * 64;         // warp m offset
    const int wn = (wid >> 2) * 64;        // warp n offset

    auto load_stage = [&](int c, int s) {
        const int kc = c << 6;
        const uint32_t sb = sbase + (uint32_t)s * STAGE2_B;
        #pragma unroll
        for (int j = 0; j < 24; j++) {
            int i = tid + j * 256;
            const __nv_bfloat16* base;
            uint32_t dst;
            size_t off;
            if (i < 4096) {                // A tiles: 256 rows x 8 segs x2
                int tsr = i >> 11;
                int rem = i & 2047;
                int row = rem >> 3, seg = rem & 7;
                base = tsr ? Alo : Ahi;
                dst = sb + (uint32_t)tsr * A_TILE_B2
                    + SW128((uint32_t)(row * 128 + seg * 16));
                off = (size_t)(m0 + row) * K + kc + seg * 8;
            } else {                       // B tiles: 128 rows x 8 segs x2
                int i2 = i - 4096;
                int tsr = i2 >> 10;
                int rem = i2 & 1023;
                int row = rem >> 3, seg = rem & 7;
                base = tsr ? Blo : Bhi;
                dst = sb + 2 * A_TILE_B2 + (uint32_t)tsr * B_TILE_B2
                    + SW128((uint32_t)(row * 128 + seg * 16));
                off = (size_t)(n0 + row) * K + kc + seg * 8;
            }
            CP_ASYNC16(dst, (const char*)(base + off));
        }
        CP_ASYNC_COMMIT();
    };

    float acc[4][8][4];
    #pragma unroll
    for (int i = 0; i < 4; i++)
        #pragma unroll
        for (int j = 0; j < 8; j++)
            #pragma unroll
            for (int r = 0; r < 4; r++) acc[i][j][r] = 0.f;

    load_stage(0, 0);
    load_stage(1, 1);

    const int a_row = lane & 15;
    const int a_kh  = lane >> 4;           // *16B within k
    const int b_q   = lane >> 3;
    const int b_n   = ((b_q >> 1) * 8) + (lane & 7);
    const uint32_t b_kB = (uint32_t)((b_q & 1) * 16);

    for (int c = 0; c < NC; c++) {
        if (c + 1 < NC) CP_ASYNC_WAIT(1);
        else            CP_ASYNC_WAIT(0);
        __syncthreads();

        const uint32_t sb = sbase + (uint32_t)(c & 1) * STAGE2_B;
        const uint32_t sAh = sb;
        const uint32_t sAl = sb + A_TILE_B2;
        const uint32_t sBh = sb + 2 * A_TILE_B2;
        const uint32_t sBl = sb + 2 * A_TILE_B2 + B_TILE_B2;

        #pragma unroll
        for (int ks = 0; ks < 4; ks++) {
            const uint32_t kB = (uint32_t)(ks * 32) + a_kh * 16;
            uint32_t ah[4][4], al[4][4];
            #pragma unroll
            for (int mt = 0; mt < 4; mt++) {
                uint32_t ra = SW128((uint32_t)(wm + mt * 16 + a_row) * 128 + kB);
                LDSM_X4(ah[mt][0], ah[mt][1], ah[mt][2], ah[mt][3], sAh + ra);
                LDSM_X4(al[mt][0], al[mt][1], al[mt][2], al[mt][3], sAl + ra);
            }
            const uint32_t kBb = (uint32_t)(ks * 32) + b_kB;
            #pragma unroll
            for (int nn = 0; nn < 4; nn++) {
                uint32_t bh[2][2], bl[2][2];
                uint32_t rb = SW128((uint32_t)(wn + nn * 16 + b_n) * 128 + kBb);
                LDSM_X4(bh[0][0], bh[0][1], bh[1][0], bh[1][1], sBh + rb);
                LDSM_X4(bl[0][0], bl[0][1], bl[1][0], bl[1][1], sBl + rb);
                #pragma unroll
                for (int half = 0; half < 2; half++) {
                    const int j = nn * 2 + half;
                    #pragma unroll
                    for (int mt = 0; mt < 4; mt++) {
                        float* cc = acc[mt][j];
                        MMA_BF16(cc, ah[mt], bh[half]);
                        MMA_BF16(cc, ah[mt], bl[half]);
                        MMA_BF16(cc, al[mt], bh[half]);
                    }
                }
            }
        }
        __syncthreads();
        if (c + 2 < NC) load_stage(c + 2, c & 1);
    }

    // Epilogue: acc[mt][j] -> rows m0+wm+mt*16+{g,g+8}, cols n0+wn+j*8+t*2
    const int g = lane >> 2;
    const int t = lane & 3;
    #pragma unroll
    for (int mt = 0; mt < 4; mt++) {
        #pragma unroll
        for (int j = 0; j < 8; j++) {
            const int col = n0 + wn + j * 8 + t * 2;
            const float bx = bias[col], by = bias[col + 1];
            const int r0 = m0 + wm + mt * 16 + g;
            float v00 = acc[mt][j][0] + bx, v01 = acc[mt][j][1] + by;
            float v10 = acc[mt][j][2] + bx, v11 = acc[mt][j][3] + by;
            if (Cf) {
                *(float2*)&Cf[(size_t)r0 * N + col] = make_float2(v00, v01);
                *(float2*)&Cf[(size_t)(r0 + 8) * N + col] = make_float2(v10, v11);
            } else {
                uint32_t h0 = pack_bf2(v00, v01);
                uint32_t h1 = pack_bf2(v10, v11);
                __nv_bfloat162 hh;
                hh = *(__nv_bfloat162*)&h0;
                uint32_t l0 = pack_bf2(v00 - __bfloat162float(hh.x),
                                       v01 - __bfloat162float(hh.y));
                hh = *(__nv_bfloat162*)&h1;
                uint32_t l1 = pack_bf2(v10 - __bfloat162float(hh.x),
                                       v11 - __bfloat162float(hh.y));
                *(uint32_t*)&Chi[(size_t)r0 * N + col] = h0;
                *(uint32_t*)&Chi[(size_t)(r0 + 8) * N + col] = h1;
                *(uint32_t*)&Clo[(size_t)r0 * N + col] = l0;
                *(uint32_t*)&Clo[(size_t)(r0 + 8) * N + col] = l1;
            }
        }
    }
}

// ---------------------------------------------------------------------------
// Flash attention on tensor cores (split bf16, causal + padding).
// Grid: (16, B*H), 256 threads = 8 warps. Q tile 128, K tile 64, D=64.
// ---------------------------------------------------------------------------
#define RS 144                       // smem row stride bytes (72 bf16)
#define Q_TILE_B (128 * RS)          // 18432
#define KV_TILE_B (64 * RS)          // 9216
#define KV_STAGE_B (4 * KV_TILE_B)   // 36864
#define ATTN_SMEM (2 * Q_TILE_B + 2 * KV_STAGE_B)  // 110592
#define SCALE2 0.1803368801111243f   // 0.125 * log2(e)

__global__ __launch_bounds__(256, 1) void attn_mma(
    const __nv_bfloat16* __restrict__ qkvhi, const __nv_bfloat16* __restrict__ qkvlo,
    const unsigned char* __restrict__ pmask,
    __nv_bfloat16* __restrict__ ahi, __nv_bfloat16* __restrict__ alo)
{
    extern __shared__ __align__(256) char smem[];
    const uint32_t sbase = smem_u32(smem);
    const int qt = gridDim.x - 1 - blockIdx.x;     // big tiles first
    const int bh = blockIdx.y;
    const int b = bh >> 4, h = bh & 15;
    const int tid = threadIdx.x;
    const int wid = tid >> 5;
    const int lane = tid & 31;
    const int wm = wid * 16;
    const int qbase = qt * 128;
    const int nkt = 2 * qt + 2;

    const uint32_t sQH = sbase;
    const uint32_t sQL = sbase + Q_TILE_B;
    const uint32_t sKV = sbase + 2 * Q_TILE_B;

    const size_t rb = (size_t)b * SEQ;
    const __nv_bfloat16* qh_g = qkvhi + rb * THREEF + h * HDIM;
    const __nv_bfloat16* ql_g = qkvlo + rb * THREEF + h * HDIM;
    const __nv_bfloat16* kh_g = qh_g + FDIM;
    const __nv_bfloat16* kl_g = ql_g + FDIM;
    const __nv_bfloat16* vh_g = qh_g + 2 * FDIM;
    const __nv_bfloat16* vl_g = ql_g + 2 * FDIM;

    auto load_kv = [&](int kt_, int s_) {
        const int kb_ = kt_ * 64;
        const uint32_t sb = sKV + (uint32_t)s_ * KV_STAGE_B;
        #pragma unroll
        for (int t = 0; t < 8; t++) {
            int i = tid + t * 256;
            int tsr = i >> 9;
            int rem = i & 511;
            int row = rem >> 3, seg = rem & 7;
            const __nv_bfloat16* g =
                (tsr == 0) ? kh_g : (tsr == 1) ? kl_g : (tsr == 2) ? vh_g : vl_g;
            const char* src = (const char*)(g + (size_t)(kb_ + row) * THREEF + seg * 8);
            uint32_t dst = sb + (uint32_t)tsr * KV_TILE_B + (uint32_t)row * RS + seg * 16;
            CP_ASYNC16(dst, src);
        }
    };

    {
        #pragma unroll
        for (int t = 0; t < 8; t++) {
            int i = tid + t * 256;
            int tsr = i >> 10;
            int rem = i & 1023;
            int row = rem >> 3, seg = rem & 7;
            const __nv_bfloat16* g = tsr ? ql_g : qh_g;
            const char* src = (const char*)(g + (size_t)(qbase + row) * THREEF + seg * 8);
            uint32_t dst = (tsr ? sQL : sQH) + (uint32_t)row * RS + seg * 16;
            CP_ASYNC16(dst, src);
        }
        load_kv(0, 0);
        CP_ASYNC_COMMIT();
    }
    CP_ASYNC_WAIT(0);
    __syncthreads();

    const int a_row = lane & 15;
    const int a_kh  = lane >> 4;
    uint32_t qfh[4][4], qfl[4][4];
    #pragma unroll
    for (int ks = 0; ks < 4; ks++) {
        uint32_t ra = (uint32_t)(wm + a_row) * RS + ks * 32 + a_kh * 16;
        LDSM_X4(qfh[ks][0], qfh[ks][1], qfh[ks][2], qfh[ks][3], sQH + ra);
        LDSM_X4(qfl[ks][0], qfl[ks][1], qfl[ks][2], qfl[ks][3], sQL + ra);
    }

    float O[8][4];
    #pragma unroll
    for (int j = 0; j < 8; j++)
        #pragma unroll
        for (int r = 0; r < 4; r++) O[j][r] = 0.f;
    float m2[2] = {-1e30f, -1e30f};
    float l_[2] = {0.f, 0.f};

    const int b_q = lane >> 3;
    const int b_n = ((b_q >> 1) * 8) + (lane & 7);
    const uint32_t b_koffB = (uint32_t)((b_q & 1) * 16);
    const int r_lo = qbase + wm + (lane >> 2);
    const int r_hi = r_lo + 8;
    const int t2 = (lane & 3) * 2;

    for (int kt = 0; kt < nkt; kt++) {
        const int kb = kt * 64;
        const int s = kt & 1;
        if (kt + 1 < nkt) { load_kv(kt + 1, s ^ 1); CP_ASYNC_COMMIT(); }

        const uint32_t sKH = sKV + (uint32_t)s * KV_STAGE_B;
        const uint32_t sKL = sKH + KV_TILE_B;
        const uint32_t sVH = sKH + 2 * KV_TILE_B;
        const uint32_t sVL = sKH + 3 * KV_TILE_B;

        float S_[8][4];
        #pragma unroll
        for (int j = 0; j < 8; j++)
            #pragma unroll
            for (int r = 0; r < 4; r++) S_[j][r] = 0.f;

        #pragma unroll
        for (int ks = 0; ks < 4; ks++) {
            #pragma unroll
            for (int g4 = 0; g4 < 4; g4++) {
                uint32_t kh0, kh1, kh2, kh3, kl0, kl1, kl2, kl3;
                uint32_t raK = (uint32_t)(g4 * 16 + b_n) * RS + ks * 32 + b_koffB;
                LDSM_X4(kh0, kh1, kh2, kh3, sKH + raK);
                LDSM_X4(kl0, kl1, kl2, kl3, sKL + raK);
                uint32_t bh0[2] = {kh0, kh1}, bh1[2] = {kh2, kh3};
                uint32_t bl0[2] = {kl0, kl1}, bl1[2] = {kl2, kl3};
                MMA_BF16(S_[2 * g4], qfh[ks], bh0);
                MMA_BF16(S_[2 * g4], qfh[ks], bl0);
                MMA_BF16(S_[2 * g4], qfl[ks], bh0);
                MMA_BF16(S_[2 * g4 + 1], qfh[ks], bh1);
                MMA_BF16(S_[2 * g4 + 1], qfh[ks], bl1);
                MMA_BF16(S_[2 * g4 + 1], qfl[ks], bh1);
            }
        }

        #pragma unroll
        for (int j = 0; j < 8; j++) {
            const int colb = kb + j * 8 + t2;
            unsigned short pm = *(const unsigned short*)(pmask + rb + colb);
            const bool p0 = pm & 0xFF, p1 = pm >> 8;
            S_[j][0] = (p0 || colb > r_lo)     ? -1e30f : S_[j][0] * SCALE2;
            S_[j][1] = (p1 || colb + 1 > r_lo) ? -1e30f : S_[j][1] * SCALE2;
            S_[j][2] = (p0 || colb > r_hi)     ? -1e30f : S_[j][2] * SCALE2;
            S_[j][3] = (p1 || colb + 1 > r_hi) ? -1e30f : S_[j][3] * SCALE2;
        }

        float mx0 = -1e30f, mx1 = -1e30f;
        #pragma unroll
        for (int j = 0; j < 8; j++) {
            mx0 = fmaxf(mx0, fmaxf(S_[j][0], S_[j][1]));
            mx1 = fmaxf(mx1, fmaxf(S_[j][2], S_[j][3]));
        }
        mx0 = fmaxf(mx0, __shfl_xor_sync(0xffffffffu, mx0, 1));
        mx0 = fmaxf(mx0, __shfl_xor_sync(0xffffffffu, mx0, 2));
        mx1 = fmaxf(mx1, __shfl_xor_sync(0xffffffffu, mx1, 1));
        mx1 = fmaxf(mx1, __shfl_xor_sync(0xffffffffu, mx1, 2));
        const float mn0 = fmaxf(m2[0], mx0);
        const float mn1 = fmaxf(m2[1], mx1);
        const float al0 = exp2_fast(m2[0] - mn0);
        const float al1 = exp2_fast(m2[1] - mn1);
        m2[0] = mn0; m2[1] = mn1;

        float sum0 = 0.f, sum1 = 0.f;
        #pragma unroll
        for (int j = 0; j < 8; j++) {
            S_[j][0] = exp2_fast(S_[j][0] - mn0);
            S_[j][1] = exp2_fast(S_[j][1] - mn0);
            S_[j][2] = exp2_fast(S_[j][2] - mn1);
            S_[j][3] = exp2_fast(S_[j][3] - mn1);
            sum0 += S_[j][0] + S_[j][1];
            sum1 += S_[j][2] + S_[j][3];
        }
        sum0 += __shfl_xor_sync(0xffffffffu, sum0, 1);
        sum0 += __shfl_xor_sync(0xffffffffu, sum0, 2);
        sum1 += __shfl_xor_sync(0xffffffffu, sum1, 1);
        sum1 += __shfl_xor_sync(0xffffffffu, sum1, 2);
        l_[0] = l_[0] * al0 + sum0;
        l_[1] = l_[1] * al1 + sum1;

        #pragma unroll
        for (int j = 0; j < 8; j++) {
            O[j][0] *= al0; O[j][1] *= al0;
            O[j][2] *= al1; O[j][3] *= al1;
        }

        #pragma unroll
        for (int kk = 0; kk < 4; kk++) {
            float a00 = S_[2 * kk][0],     a01 = S_[2 * kk][1];
            float a10 = S_[2 * kk][2],     a11 = S_[2 * kk][3];
            float a20 = S_[2 * kk + 1][0], a21 = S_[2 * kk + 1][1];
            float a30 = S_[2 * kk + 1][2], a31 = S_[2 * kk + 1][3];
            uint32_t ph[4], pl[4];
            ph[0] = pack_bf2(a00, a01);
            ph[1] = pack_bf2(a10, a11);
            ph[2] = pack_bf2(a20, a21);
            ph[3] = pack_bf2(a30, a31);
            __nv_bfloat162 h;
            h = *(__nv_bfloat162*)&ph[0];
            pl[0] = pack_bf2(a00 - __bfloat162float(h.x), a01 - __bfloat162float(h.y));
            h = *(__nv_bfloat162*)&ph[1];
            pl[1] = pack_bf2(a10 - __bfloat162float(h.x), a11 - __bfloat162float(h.y));
            h = *(__nv_bfloat162*)&ph[2];
            pl[2] = pack_bf2(a20 - __bfloat162float(h.x), a21 - __bfloat162float(h.y));
            h = *(__nv_bfloat162*)&ph[3];
            pl[3] = pack_bf2(a30 - __bfloat162float(h.x), a31 - __bfloat162float(h.y));

            #pragma unroll
            for (int dp = 0; dp < 4; dp++) {
                uint32_t raV = (uint32_t)(kk * 16 + (lane & 15)) * RS
                             + (uint32_t)(dp * 32 + (lane >> 4) * 16);
                uint32_t v0, v1, v2, v3, w0, w1, w2, w3;
                LDSM_X4_T(v0, v1, v2, v3, sVH + raV);
                LDSM_X4_T(w0, w1, w2, w3, sVL + raV);
                uint32_t bh0[2] = {v0, v1}, bh1[2] = {v2, v3};
                uint32_t bl0[2] = {w0, w1}, bl1[2] = {w2, w3};
                MMA_BF16(O[dp * 2],     ph, bh0);
                MMA_BF16(O[dp * 2],     pl, bh0);
                MMA_BF16(O[dp * 2],     ph, bl0);
                MMA_BF16(O[dp * 2 + 1], ph, bh1);
                MMA_BF16(O[dp * 2 + 1], pl, bh1);
                MMA_BF16(O[dp * 2 + 1], ph, bl1);
            }
        }

        if (kt + 1 < nkt) { CP_ASYNC_WAIT(0); __syncthreads(); }
    }

    const float inv0 = 1.f / l_[0];
    const float inv1 = 1.f / l_[1];
    const size_t row0 = rb + (size_t)r_lo;
    const size_t row1 = rb + (size_t)r_hi;
    #pragma unroll
    for (int j = 0; j < 8; j++) {
        const int col = h * HDIM + j * 8 + t2;
        float v00 = O[j][0] * inv0, v01 = O[j][1] * inv0;
        float v10 = O[j][2] * inv1, v11 = O[j][3] * inv1;
        uint32_t h0 = pack_bf2(v00, v01);
        uint32_t h1 = pack_bf2(v10, v11);
        __nv_bfloat162 hh;
        hh = *(__nv_bfloat162*)&h0;
        uint32_t l0 = pack_bf2(v00 - __bfloat162float(hh.x), v01 - __bfloat162float(hh.y));
        hh = *(__nv_bfloat162*)&h1;
        uint32_t l1 = pack_bf2(v10 - __bfloat162float(hh.x), v11 - __bfloat162float(hh.y));
        *(uint32_t*)&ahi[row0 * FDIM + col] = h0;
        *(uint32_t*)&ahi[row1 * FDIM + col] = h1;
        *(uint32_t*)&alo[row0 * FDIM + col] = l0;
        *(uint32_t*)&alo[row1 * FDIM + col] = l1;
    }
}

// ---------------------------------------------------------------------------
// Launch
// ---------------------------------------------------------------------------
extern "C" void kernel_launch(void* const* d_in, const int* in_sizes, int n_in,
                              void* d_out, int out_size)
{
    (void)in_sizes; (void)n_in; (void)out_size;
    const float* x      = (const float*)d_in[0];
    const unsigned char* pmask = (const unsigned char*)d_in[1];
    const float* qkv_w  = (const float*)d_in[2];
    const float* qkv_b  = (const float*)d_in[3];
    const float* out_w  = (const float*)d_in[4];
    const float* out_b  = (const float*)d_in[5];
    float* out = (float*)d_out;

    __nv_bfloat16 *xhi, *xlo, *whi, *wlo, *qkvhi, *qkvlo, *ahi, *alo, *owhi, *owlo;
    cudaGetSymbolAddress((void**)&xhi, g_xhi);
    cudaGetSymbolAddress((void**)&xlo, g_xlo);
    cudaGetSymbolAddress((void**)&whi, g_whi);
    cudaGetSymbolAddress((void**)&wlo, g_wlo);
    cudaGetSymbolAddress((void**)&qkvhi, g_qkvhi);
    cudaGetSymbolAddress((void**)&qkvlo, g_qkvlo);
    cudaGetSymbolAddress((void**)&ahi, g_ahi);
    cudaGetSymbolAddress((void**)&alo, g_alo);
    cudaGetSymbolAddress((void**)&owhi, g_owhi);
    cudaGetSymbolAddress((void**)&owlo, g_owlo);

    static bool attr_done = false;
    if (!attr_done) {
        cudaFuncSetAttribute(gemm_mma_split,
                             cudaFuncAttributeMaxDynamicSharedMemorySize, GEMM_SMEM);
        cudaFuncSetAttribute(attn_mma,
                             cudaFuncAttributeMaxDynamicSharedMemorySize, ATTN_SMEM);
        attr_done = true;
    }

    // Split conversions (inputs only)
    split_bf16_kernel<<<512, 256>>>(x, xhi, xlo, MROWS * FDIM / 4);
    split_bf16_kernel<<<512, 256>>>(qkv_w, whi, wlo, THREEF * FDIM / 4);
    split_bf16_kernel<<<256, 256>>>(out_w, owhi, owlo, FDIM * FDIM / 4);

    // 1) QKV projection -> split bf16 qkv  (grid: N/128 x M/256)
    gemm_mma_split<<<dim3(THREEF / 128, MROWS / 256), 256, GEMM_SMEM>>>(
        xhi, xlo, whi, wlo, qkv_b, nullptr, qkvhi, qkvlo, MROWS, THREEF, FDIM);

    // 2) Attention (tensor cores) -> split bf16 att
    attn_mma<<<dim3(SEQ / 128, BATCH * NHEAD), 256, ATTN_SMEM>>>(
        qkvhi, qkvlo, pmask, ahi, alo);

    // 3) Output projection -> fp32 out
    gemm_mma_split<<<dim3(FDIM / 128, MROWS / 256), 256, GEMM_SMEM>>>(
        ahi, alo, owhi, owlo, out_b, out, nullptr, nullptr, MROWS, FDIM, FDIM);
}

// round 6
// speedup vs baseline: 3.0400x; 1.0420x over previous
#include <cuda_runtime.h>
#include <cuda_bf16.h>
#include <cstdint>

// Problem constants
#define BATCH 2
#define SEQ   2048
#define FDIM  1024
#define NHEAD 16
#define HDIM  64
#define THREEF (3 * FDIM)     // 3072
#define MROWS (BATCH * SEQ)   // 4096

// ---------------------------------------------------------------------------
// Scratch (allocation-free rule: __device__ globals)
// ---------------------------------------------------------------------------
__device__ __align__(256) __nv_bfloat16 g_xhi[(size_t)MROWS * FDIM];
__device__ __align__(256) __nv_bfloat16 g_xlo[(size_t)MROWS * FDIM];
__device__ __align__(256) __nv_bfloat16 g_whi[(size_t)THREEF * FDIM];
__device__ __align__(256) __nv_bfloat16 g_wlo[(size_t)THREEF * FDIM];
__device__ __align__(256) __nv_bfloat16 g_qkvhi[(size_t)MROWS * THREEF];
__device__ __align__(256) __nv_bfloat16 g_qkvlo[(size_t)MROWS * THREEF];
__device__ __align__(256) __nv_bfloat16 g_ahi[(size_t)MROWS * FDIM];
__device__ __align__(256) __nv_bfloat16 g_alo[(size_t)MROWS * FDIM];
__device__ __align__(256) __nv_bfloat16 g_owhi[(size_t)FDIM * FDIM];
__device__ __align__(256) __nv_bfloat16 g_owlo[(size_t)FDIM * FDIM];

// ---------------------------------------------------------------------------
// PTX helpers (base sm_100-compatible: cp.async, ldmatrix, mma.sync)
// ---------------------------------------------------------------------------
__device__ __forceinline__ uint32_t smem_u32(const void* p) {
    uint32_t a;
    asm("{ .reg .u64 t; cvta.to.shared.u64 t, %1; cvt.u32.u64 %0, t; }"
        : "=r"(a) : "l"(p));
    return a;
}

#define CP_ASYNC16(dst, src) \
    asm volatile("cp.async.cg.shared.global [%0], [%1], 16;" \
                 :: "r"((uint32_t)(dst)), "l"(src) : "memory")
#define CP_ASYNC_COMMIT() asm volatile("cp.async.commit_group;" ::: "memory")
#define CP_ASYNC_WAIT(n)  asm volatile("cp.async.wait_group %0;" :: "n"(n) : "memory")

#define LDSM_X4(r0, r1, r2, r3, addr) \
    asm volatile("ldmatrix.sync.aligned.m8n8.x4.shared.b16 {%0,%1,%2,%3}, [%4];" \
                 : "=r"(r0), "=r"(r1), "=r"(r2), "=r"(r3) : "r"(addr))

#define LDSM_X4_T(r0, r1, r2, r3, addr) \
    asm volatile("ldmatrix.sync.aligned.m8n8.x4.trans.shared.b16 {%0,%1,%2,%3}, [%4];" \
                 : "=r"(r0), "=r"(r1), "=r"(r2), "=r"(r3) : "r"(addr))

#define MMA_BF16(c, a, b) \
    asm volatile( \
        "mma.sync.aligned.m16n8k16.row.col.f32.bf16.bf16.f32 " \
        "{%0,%1,%2,%3}, {%4,%5,%6,%7}, {%8,%9}, {%0,%1,%2,%3};" \
        : "+f"((c)[0]), "+f"((c)[1]), "+f"((c)[2]), "+f"((c)[3]) \
        : "r"((a)[0]), "r"((a)[1]), "r"((a)[2]), "r"((a)[3]), \
          "r"((b)[0]), "r"((b)[1]))

__device__ __forceinline__ uint32_t pack_bf2(float a, float b) {
    __nv_bfloat162 h = __floats2bfloat162_rn(a, b);
    return *reinterpret_cast<uint32_t*>(&h);
}

// SW128 swizzle: XOR 16B-segment bits [4:6] with row bits [7:9]
#define SW128(off) ((off) ^ (((off) >> 3) & 0x70))

// MUFU-based 2^x (single EX2 instruction; frees the FMA pipe)
__device__ __forceinline__ float ex2f(float x) {
    float y;
    asm("ex2.approx.f32 %0, %1;" : "=f"(y) : "f"(x));
    return y;
}

// ---------------------------------------------------------------------------
// fp32 -> (bf16 hi, bf16 lo) split conversion (fused: x, qkv_w, out_w)
// ---------------------------------------------------------------------------
#define XN4   (MROWS * FDIM / 4)
#define WN4   (THREEF * FDIM / 4)
#define OWN4  (FDIM * FDIM / 4)

__global__ void split_all_kernel(const float* __restrict__ x,
                                 const float* __restrict__ w,
                                 const float* __restrict__ ow,
                                 __nv_bfloat16* __restrict__ xhi, __nv_bfloat16* __restrict__ xlo,
                                 __nv_bfloat16* __restrict__ whi, __nv_bfloat16* __restrict__ wlo,
                                 __nv_bfloat16* __restrict__ owhi, __nv_bfloat16* __restrict__ owlo)
{
    const int total = XN4 + WN4 + OWN4;
    for (int i = blockIdx.x * blockDim.x + threadIdx.x; i < total;
         i += gridDim.x * blockDim.x) {
        const float* in;
        __nv_bfloat16 *hi, *lo;
        int idx = i;
        if (idx < XN4) { in = x; hi = xhi; lo = xlo; }
        else if (idx < XN4 + WN4) { idx -= XN4; in = w; hi = whi; lo = wlo; }
        else { idx -= XN4 + WN4; in = ow; hi = owhi; lo = owlo; }
        float4 v = ((const float4*)in)[idx];
        __nv_bfloat16 hx = __float2bfloat16_rn(v.x);
        __nv_bfloat16 hy = __float2bfloat16_rn(v.y);
        __nv_bfloat16 hz = __float2bfloat16_rn(v.z);
        __nv_bfloat16 hw = __float2bfloat16_rn(v.w);
        __nv_bfloat162 h0; h0.x = hx; h0.y = hy;
        __nv_bfloat162 h1; h1.x = hz; h1.y = hw;
        __nv_bfloat162 l0, l1;
        l0.x = __float2bfloat16_rn(v.x - __bfloat162float(hx));
        l0.y = __float2bfloat16_rn(v.y - __bfloat162float(hy));
        l1.x = __float2bfloat16_rn(v.z - __bfloat162float(hz));
        l1.y = __float2bfloat16_rn(v.w - __bfloat162float(hw));
        ((__nv_bfloat162*)hi)[idx * 2 + 0] = h0;
        ((__nv_bfloat162*)hi)[idx * 2 + 1] = h1;
        ((__nv_bfloat162*)lo)[idx * 2 + 0] = l0;
        ((__nv_bfloat162*)lo)[idx * 2 + 1] = l1;
    }
}

// ---------------------------------------------------------------------------
// Split-bf16 tensor-core GEMM (NT): C = A*W^T + bias
// CTA tile 256(M) x 128(N), BK=64, warp tile 64x64 (8 warps, 4x2).
// Pass-outer MMA ordering: same-accumulator reuse distance = 8.
// ---------------------------------------------------------------------------
#define A_TILE_B2 (256 * 128)                     // 32768 per tensor
#define B_TILE_B2 (128 * 128)                     // 16384 per tensor
#define STAGE2_B (2 * A_TILE_B2 + 2 * B_TILE_B2)  // 98304
#define GEMM_SMEM (2 * STAGE2_B)                  // 196608

__global__ __launch_bounds__(256, 1) void gemm_mma_split(
    const __nv_bfloat16* __restrict__ Ahi, const __nv_bfloat16* __restrict__ Alo,
    const __nv_bfloat16* __restrict__ Bhi, const __nv_bfloat16* __restrict__ Blo,
    const float* __restrict__ bias, float* __restrict__ Cf,
    __nv_bfloat16* __restrict__ Chi, __nv_bfloat16* __restrict__ Clo,
    int M, int N, int K)
{
    extern __shared__ __align__(256) char smem[];
    const uint32_t sbase = smem_u32(smem);
    const int tid = threadIdx.x;
    const int wid = tid >> 5;
    const int lane = tid & 31;
    const int m0 = blockIdx.y * 256;
    const int n0 = blockIdx.x * 128;
    const int NC = K >> 6;                 // chunks of 64

    const int wm = (wid & 3) * 64;
    const int wn = (wid >> 2) * 64;

    auto load_stage = [&](int c, int s) {
        const int kc = c << 6;
        const uint32_t sb = sbase + (uint32_t)s * STAGE2_B;
        #pragma unroll
        for (int j = 0; j < 24; j++) {
            int i = tid + j * 256;
            const __nv_bfloat16* base;
            uint32_t dst;
            size_t off;
            if (i < 4096) {
                int tsr = i >> 11;
                int rem = i & 2047;
                int row = rem >> 3, seg = rem & 7;
                base = tsr ? Alo : Ahi;
                dst = sb + (uint32_t)tsr * A_TILE_B2
                    + SW128((uint32_t)(row * 128 + seg * 16));
                off = (size_t)(m0 + row) * K + kc + seg * 8;
            } else {
                int i2 = i - 4096;
                int tsr = i2 >> 10;
                int rem = i2 & 1023;
                int row = rem >> 3, seg = rem & 7;
                base = tsr ? Blo : Bhi;
                dst = sb + 2 * A_TILE_B2 + (uint32_t)tsr * B_TILE_B2
                    + SW128((uint32_t)(row * 128 + seg * 16));
                off = (size_t)(n0 + row) * K + kc + seg * 8;
            }
            CP_ASYNC16(dst, (const char*)(base + off));
        }
        CP_ASYNC_COMMIT();
    };

    float acc[4][8][4];
    #pragma unroll
    for (int i = 0; i < 4; i++)
        #pragma unroll
        for (int j = 0; j < 8; j++)
            #pragma unroll
            for (int r = 0; r < 4; r++) acc[i][j][r] = 0.f;

    load_stage(0, 0);
    load_stage(1, 1);

    const int a_row = lane & 15;
    const int a_kh  = lane >> 4;
    const int b_q   = lane >> 3;
    const int b_n   = ((b_q >> 1) * 8) + (lane & 7);
    const uint32_t b_kB = (uint32_t)((b_q & 1) * 16);

    for (int c = 0; c < NC; c++) {
        if (c + 1 < NC) CP_ASYNC_WAIT(1);
        else            CP_ASYNC_WAIT(0);
        __syncthreads();

        const uint32_t sb = sbase + (uint32_t)(c & 1) * STAGE2_B;
        const uint32_t sAh = sb;
        const uint32_t sAl = sb + A_TILE_B2;
        const uint32_t sBh = sb + 2 * A_TILE_B2;
        const uint32_t sBl = sb + 2 * A_TILE_B2 + B_TILE_B2;

        #pragma unroll
        for (int ks = 0; ks < 4; ks++) {
            const uint32_t kB = (uint32_t)(ks * 32) + a_kh * 16;
            uint32_t ah[4][4], al[4][4];
            #pragma unroll
            for (int mt = 0; mt < 4; mt++) {
                uint32_t ra = SW128((uint32_t)(wm + mt * 16 + a_row) * 128 + kB);
                LDSM_X4(ah[mt][0], ah[mt][1], ah[mt][2], ah[mt][3], sAh + ra);
                LDSM_X4(al[mt][0], al[mt][1], al[mt][2], al[mt][3], sAl + ra);
            }
            const uint32_t kBb = (uint32_t)(ks * 32) + b_kB;
            #pragma unroll
            for (int nn = 0; nn < 4; nn++) {
                uint32_t bh[2][2], bl[2][2];
                uint32_t rbo = SW128((uint32_t)(wn + nn * 16 + b_n) * 128 + kBb);
                LDSM_X4(bh[0][0], bh[0][1], bh[1][0], bh[1][1], sBh + rbo);
                LDSM_X4(bl[0][0], bl[0][1], bl[1][0], bl[1][1], sBl + rbo);
                // Pass-outer: 8 MMAs between same-accumulator reuses
                #pragma unroll
                for (int p = 0; p < 3; p++) {
                    #pragma unroll
                    for (int half = 0; half < 2; half++) {
                        const int j = nn * 2 + half;
                        #pragma unroll
                        for (int mt = 0; mt < 4; mt++) {
                            float* cc = acc[mt][j];
                            if (p == 0)      MMA_BF16(cc, ah[mt], bh[half]);
                            else if (p == 1) MMA_BF16(cc, ah[mt], bl[half]);
                            else             MMA_BF16(cc, al[mt], bh[half]);
                        }
                    }
                }
            }
        }
        __syncthreads();
        if (c + 2 < NC) load_stage(c + 2, c & 1);
    }

    const int g = lane >> 2;
    const int t = lane & 3;
    #pragma unroll
    for (int mt = 0; mt < 4; mt++) {
        #pragma unroll
        for (int j = 0; j < 8; j++) {
            const int col = n0 + wn + j * 8 + t * 2;
            const float bx = bias[col], by = bias[col + 1];
            const int r0 = m0 + wm + mt * 16 + g;
            float v00 = acc[mt][j][0] + bx, v01 = acc[mt][j][1] + by;
            float v10 = acc[mt][j][2] + bx, v11 = acc[mt][j][3] + by;
            if (Cf) {
                *(float2*)&Cf[(size_t)r0 * N + col] = make_float2(v00, v01);
                *(float2*)&Cf[(size_t)(r0 + 8) * N + col] = make_float2(v10, v11);
            } else {
                uint32_t h0 = pack_bf2(v00, v01);
                uint32_t h1 = pack_bf2(v10, v11);
                __nv_bfloat162 hh;
                hh = *(__nv_bfloat162*)&h0;
                uint32_t l0 = pack_bf2(v00 - __bfloat162float(hh.x),
                                       v01 - __bfloat162float(hh.y));
                hh = *(__nv_bfloat162*)&h1;
                uint32_t l1 = pack_bf2(v10 - __bfloat162float(hh.x),
                                       v11 - __bfloat162float(hh.y));
                *(uint32_t*)&Chi[(size_t)r0 * N + col] = h0;
                *(uint32_t*)&Chi[(size_t)(r0 + 8) * N + col] = h1;
                *(uint32_t*)&Clo[(size_t)r0 * N + col] = l0;
                *(uint32_t*)&Clo[(size_t)(r0 + 8) * N + col] = l1;
            }
        }
    }
}

// ---------------------------------------------------------------------------
// Flash attention on tensor cores (split bf16, causal + padding).
// Grid: (16, B*H), 256 threads = 8 warps. Q tile 128, K tile 64, D=64.
// ---------------------------------------------------------------------------
#define RS 144                       // smem row stride bytes (72 bf16)
#define Q_TILE_B (128 * RS)          // 18432
#define KV_TILE_B (64 * RS)          // 9216
#define KV_STAGE_B (4 * KV_TILE_B)   // 36864
#define ATTN_SMEM (2 * Q_TILE_B + 2 * KV_STAGE_B)  // 110592
#define SCALE2 0.1803368801111243f   // 0.125 * log2(e)

__global__ __launch_bounds__(256, 1) void attn_mma(
    const __nv_bfloat16* __restrict__ qkvhi, const __nv_bfloat16* __restrict__ qkvlo,
    const unsigned char* __restrict__ pmask,
    __nv_bfloat16* __restrict__ ahi, __nv_bfloat16* __restrict__ alo)
{
    extern __shared__ __align__(256) char smem[];
    const uint32_t sbase = smem_u32(smem);
    const int qt = gridDim.x - 1 - blockIdx.x;     // big tiles first
    const int bh = blockIdx.y;
    const int b = bh >> 4, h = bh & 15;
    const int tid = threadIdx.x;
    const int wid = tid >> 5;
    const int lane = tid & 31;
    const int wm = wid * 16;
    const int qbase = qt * 128;
    const int nkt = 2 * qt + 2;

    const uint32_t sQH = sbase;
    const uint32_t sQL = sbase + Q_TILE_B;
    const uint32_t sKV = sbase + 2 * Q_TILE_B;

    const size_t rb = (size_t)b * SEQ;
    const __nv_bfloat16* qh_g = qkvhi + rb * THREEF + h * HDIM;
    const __nv_bfloat16* ql_g = qkvlo + rb * THREEF + h * HDIM;
    const __nv_bfloat16* kh_g = qh_g + FDIM;
    const __nv_bfloat16* kl_g = ql_g + FDIM;
    const __nv_bfloat16* vh_g = qh_g + 2 * FDIM;
    const __nv_bfloat16* vl_g = ql_g + 2 * FDIM;

    auto load_kv = [&](int kt_, int s_) {
        const int kb_ = kt_ * 64;
        const uint32_t sb = sKV + (uint32_t)s_ * KV_STAGE_B;
        #pragma unroll
        for (int t = 0; t < 8; t++) {
            int i = tid + t * 256;
            int tsr = i >> 9;
            int rem = i & 511;
            int row = rem >> 3, seg = rem & 7;
            const __nv_bfloat16* g =
                (tsr == 0) ? kh_g : (tsr == 1) ? kl_g : (tsr == 2) ? vh_g : vl_g;
            const char* src = (const char*)(g + (size_t)(kb_ + row) * THREEF + seg * 8);
            uint32_t dst = sb + (uint32_t)tsr * KV_TILE_B + (uint32_t)row * RS + seg * 16;
            CP_ASYNC16(dst, src);
        }
    };

    {
        #pragma unroll
        for (int t = 0; t < 8; t++) {
            int i = tid + t * 256;
            int tsr = i >> 10;
            int rem = i & 1023;
            int row = rem >> 3, seg = rem & 7;
            const __nv_bfloat16* g = tsr ? ql_g : qh_g;
            const char* src = (const char*)(g + (size_t)(qbase + row) * THREEF + seg * 8);
            uint32_t dst = (tsr ? sQL : sQH) + (uint32_t)row * RS + seg * 16;
            CP_ASYNC16(dst, src);
        }
        load_kv(0, 0);
        CP_ASYNC_COMMIT();
    }
    CP_ASYNC_WAIT(0);
    __syncthreads();

    const int a_row = lane & 15;
    const int a_kh  = lane >> 4;
    uint32_t qfh[4][4], qfl[4][4];
    #pragma unroll
    for (int ks = 0; ks < 4; ks++) {
        uint32_t ra = (uint32_t)(wm + a_row) * RS + ks * 32 + a_kh * 16;
        LDSM_X4(qfh[ks][0], qfh[ks][1], qfh[ks][2], qfh[ks][3], sQH + ra);
        LDSM_X4(qfl[ks][0], qfl[ks][1], qfl[ks][2], qfl[ks][3], sQL + ra);
    }

    float O[8][4];
    #pragma unroll
    for (int j = 0; j < 8; j++)
        #pragma unroll
        for (int r = 0; r < 4; r++) O[j][r] = 0.f;
    float m2[2] = {-1e30f, -1e30f};
    float l_[2] = {0.f, 0.f};

    const int b_q = lane >> 3;
    const int b_n = ((b_q >> 1) * 8) + (lane & 7);
    const uint32_t b_koffB = (uint32_t)((b_q & 1) * 16);
    const int r_lo = qbase + wm + (lane >> 2);
    const int r_hi = r_lo + 8;
    const int t2 = (lane & 3) * 2;

    for (int kt = 0; kt < nkt; kt++) {
        const int kb = kt * 64;
        const int s = kt & 1;
        if (kt + 1 < nkt) { load_kv(kt + 1, s ^ 1); CP_ASYNC_COMMIT(); }

        const uint32_t sKH = sKV + (uint32_t)s * KV_STAGE_B;
        const uint32_t sKL = sKH + KV_TILE_B;
        const uint32_t sVH = sKH + 2 * KV_TILE_B;
        const uint32_t sVL = sKH + 3 * KV_TILE_B;

        float S_[8][4];
        #pragma unroll
        for (int j = 0; j < 8; j++)
            #pragma unroll
            for (int r = 0; r < 4; r++) S_[j][r] = 0.f;

        // ---- S = Q K^T: load all K frags, then pass-outer MMAs ----
        #pragma unroll
        for (int ks = 0; ks < 4; ks++) {
            uint32_t kh[4][4], kl[4][4];
            #pragma unroll
            for (int g4 = 0; g4 < 4; g4++) {
                uint32_t raK = (uint32_t)(g4 * 16 + b_n) * RS + ks * 32 + b_koffB;
                LDSM_X4(kh[g4][0], kh[g4][1], kh[g4][2], kh[g4][3], sKH + raK);
                LDSM_X4(kl[g4][0], kl[g4][1], kl[g4][2], kl[g4][3], sKL + raK);
            }
            #pragma unroll
            for (int p = 0; p < 3; p++) {
                #pragma unroll
                for (int g4 = 0; g4 < 4; g4++) {
                    const uint32_t* aop = (p == 2) ? qfl[ks] : qfh[ks];
                    const uint32_t* bsrc = (p == 1) ? kl[g4] : kh[g4];
                    uint32_t b0[2] = {bsrc[0], bsrc[1]};
                    uint32_t b1[2] = {bsrc[2], bsrc[3]};
                    MMA_BF16(S_[2 * g4],     aop, b0);
                    MMA_BF16(S_[2 * g4 + 1], aop, b1);
                }
            }
        }

        #pragma unroll
        for (int j = 0; j < 8; j++) {
            const int colb = kb + j * 8 + t2;
            unsigned short pm = *(const unsigned short*)(pmask + rb + colb);
            const bool p0 = pm & 0xFF, p1 = pm >> 8;
            S_[j][0] = (p0 || colb > r_lo)     ? -1e30f : S_[j][0] * SCALE2;
            S_[j][1] = (p1 || colb + 1 > r_lo) ? -1e30f : S_[j][1] * SCALE2;
            S_[j][2] = (p0 || colb > r_hi)     ? -1e30f : S_[j][2] * SCALE2;
            S_[j][3] = (p1 || colb + 1 > r_hi) ? -1e30f : S_[j][3] * SCALE2;
        }

        float mx0 = -1e30f, mx1 = -1e30f;
        #pragma unroll
        for (int j = 0; j < 8; j++) {
            mx0 = fmaxf(mx0, fmaxf(S_[j][0], S_[j][1]));
            mx1 = fmaxf(mx1, fmaxf(S_[j][2], S_[j][3]));
        }
        mx0 = fmaxf(mx0, __shfl_xor_sync(0xffffffffu, mx0, 1));
        mx0 = fmaxf(mx0, __shfl_xor_sync(0xffffffffu, mx0, 2));
        mx1 = fmaxf(mx1, __shfl_xor_sync(0xffffffffu, mx1, 1));
        mx1 = fmaxf(mx1, __shfl_xor_sync(0xffffffffu, mx1, 2));
        const float mn0 = fmaxf(m2[0], mx0);
        const float mn1 = fmaxf(m2[1], mx1);
        const float al0 = ex2f(m2[0] - mn0);
        const float al1 = ex2f(m2[1] - mn1);
        m2[0] = mn0; m2[1] = mn1;

        float sum0 = 0.f, sum1 = 0.f;
        #pragma unroll
        for (int j = 0; j < 8; j++) {
            S_[j][0] = ex2f(S_[j][0] - mn0);
            S_[j][1] = ex2f(S_[j][1] - mn0);
            S_[j][2] = ex2f(S_[j][2] - mn1);
            S_[j][3] = ex2f(S_[j][3] - mn1);
            sum0 += S_[j][0] + S_[j][1];
            sum1 += S_[j][2] + S_[j][3];
        }
        sum0 += __shfl_xor_sync(0xffffffffu, sum0, 1);
        sum0 += __shfl_xor_sync(0xffffffffu, sum0, 2);
        sum1 += __shfl_xor_sync(0xffffffffu, sum1, 1);
        sum1 += __shfl_xor_sync(0xffffffffu, sum1, 2);
        l_[0] = l_[0] * al0 + sum0;
        l_[1] = l_[1] * al1 + sum1;

        #pragma unroll
        for (int j = 0; j < 8; j++) {
            O[j][0] *= al0; O[j][1] *= al0;
            O[j][2] *= al1; O[j][3] *= al1;
        }

        // ---- O += P V: split P in regs, preload all V frags, pass-outer ----
        #pragma unroll
        for (int kk = 0; kk < 4; kk++) {
            float a00 = S_[2 * kk][0],     a01 = S_[2 * kk][1];
            float a10 = S_[2 * kk][2],     a11 = S_[2 * kk][3];
            float a20 = S_[2 * kk + 1][0], a21 = S_[2 * kk + 1][1];
            float a30 = S_[2 * kk + 1][2], a31 = S_[2 * kk + 1][3];
            uint32_t ph[4], pl[4];
            ph[0] = pack_bf2(a00, a01);
            ph[1] = pack_bf2(a10, a11);
            ph[2] = pack_bf2(a20, a21);
            ph[3] = pack_bf2(a30, a31);
            __nv_bfloat162 hh;
            hh = *(__nv_bfloat162*)&ph[0];
            pl[0] = pack_bf2(a00 - __bfloat162float(hh.x), a01 - __bfloat162float(hh.y));
            hh = *(__nv_bfloat162*)&ph[1];
            pl[1] = pack_bf2(a10 - __bfloat162float(hh.x), a11 - __bfloat162float(hh.y));
            hh = *(__nv_bfloat162*)&ph[2];
            pl[2] = pack_bf2(a20 - __bfloat162float(hh.x), a21 - __bfloat162float(hh.y));
            hh = *(__nv_bfloat162*)&ph[3];
            pl[3] = pack_bf2(a30 - __bfloat162float(hh.x), a31 - __bfloat162float(hh.y));

            uint32_t vh[4][4], vl[4][4];
            #pragma unroll
            for (int dp = 0; dp < 4; dp++) {
                uint32_t raV = (uint32_t)(kk * 16 + (lane & 15)) * RS
                             + (uint32_t)(dp * 32 + (lane >> 4) * 16);
                LDSM_X4_T(vh[dp][0], vh[dp][1], vh[dp][2], vh[dp][3], sVH + raV);
                LDSM_X4_T(vl[dp][0], vl[dp][1], vl[dp][2], vl[dp][3], sVL + raV);
            }
            #pragma unroll
            for (int p = 0; p < 3; p++) {
                #pragma unroll
                for (int dp = 0; dp < 4; dp++) {
                    const uint32_t* aop = (p == 1) ? pl : ph;
                    const uint32_t* bsrc = (p == 2) ? vl[dp] : vh[dp];
                    uint32_t b0[2] = {bsrc[0], bsrc[1]};
                    uint32_t b1[2] = {bsrc[2], bsrc[3]};
                    MMA_BF16(O[dp * 2],     aop, b0);
                    MMA_BF16(O[dp * 2 + 1], aop, b1);
                }
            }
        }

        if (kt + 1 < nkt) { CP_ASYNC_WAIT(0); __syncthreads(); }
    }

    const float inv0 = 1.f / l_[0];
    const float inv1 = 1.f / l_[1];
    const size_t row0 = rb + (size_t)r_lo;
    const size_t row1 = rb + (size_t)r_hi;
    #pragma unroll
    for (int j = 0; j < 8; j++) {
        const int col = h * HDIM + j * 8 + t2;
        float v00 = O[j][0] * inv0, v01 = O[j][1] * inv0;
        float v10 = O[j][2] * inv1, v11 = O[j][3] * inv1;
        uint32_t h0 = pack_bf2(v00, v01);
        uint32_t h1 = pack_bf2(v10, v11);
        __nv_bfloat162 hh;
        hh = *(__nv_bfloat162*)&h0;
        uint32_t l0 = pack_bf2(v00 - __bfloat162float(hh.x), v01 - __bfloat162float(hh.y));
        hh = *(__nv_bfloat162*)&h1;
        uint32_t l1 = pack_bf2(v10 - __bfloat162float(hh.x), v11 - __bfloat162float(hh.y));
        *(uint32_t*)&ahi[row0 * FDIM + col] = h0;
        *(uint32_t*)&ahi[row1 * FDIM + col] = h1;
        *(uint32_t*)&alo[row0 * FDIM + col] = l0;
        *(uint32_t*)&alo[row1 * FDIM + col] = l1;
    }
}

// ---------------------------------------------------------------------------
// Launch
// ---------------------------------------------------------------------------
extern "C" void kernel_launch(void* const* d_in, const int* in_sizes, int n_in,
                              void* d_out, int out_size)
{
    (void)in_sizes; (void)n_in; (void)out_size;
    const float* x      = (const float*)d_in[0];
    const unsigned char* pmask = (const unsigned char*)d_in[1];
    const float* qkv_w  = (const float*)d_in[2];
    const float* qkv_b  = (const float*)d_in[3];
    const float* out_w  = (const float*)d_in[4];
    const float* out_b  = (const float*)d_in[5];
    float* out = (float*)d_out;

    __nv_bfloat16 *xhi, *xlo, *whi, *wlo, *qkvhi, *qkvlo, *ahi, *alo, *owhi, *owlo;
    cudaGetSymbolAddress((void**)&xhi, g_xhi);
    cudaGetSymbolAddress((void**)&xlo, g_xlo);
    cudaGetSymbolAddress((void**)&whi, g_whi);
    cudaGetSymbolAddress((void**)&wlo, g_wlo);
    cudaGetSymbolAddress((void**)&qkvhi, g_qkvhi);
    cudaGetSymbolAddress((void**)&qkvlo, g_qkvlo);
    cudaGetSymbolAddress((void**)&ahi, g_ahi);
    cudaGetSymbolAddress((void**)&alo, g_alo);
    cudaGetSymbolAddress((void**)&owhi, g_owhi);
    cudaGetSymbolAddress((void**)&owlo, g_owlo);

    static bool attr_done = false;
    if (!attr_done) {
        cudaFuncSetAttribute(gemm_mma_split,
                             cudaFuncAttributeMaxDynamicSharedMemorySize, GEMM_SMEM);
        cudaFuncSetAttribute(attn_mma,
                             cudaFuncAttributeMaxDynamicSharedMemorySize, ATTN_SMEM);
        attr_done = true;
    }

    // Split conversions (x, qkv_w, out_w fused)
    split_all_kernel<<<888, 256>>>(x, qkv_w, out_w, xhi, xlo, whi, wlo, owhi, owlo);

    // 1) QKV projection -> split bf16 qkv  (grid: N/128 x M/256)
    gemm_mma_split<<<dim3(THREEF / 128, MROWS / 256), 256, GEMM_SMEM>>>(
        xhi, xlo, whi, wlo, qkv_b, nullptr, qkvhi, qkvlo, MROWS, THREEF, FDIM);

    // 2) Attention (tensor cores) -> split bf16 att
    attn_mma<<<dim3(SEQ / 128, BATCH * NHEAD), 256, ATTN_SMEM>>>(
        qkvhi, qkvlo, pmask, ahi, alo);

    // 3) Output projection -> fp32 out
    gemm_mma_split<<<dim3(FDIM / 128, MROWS / 256), 256, GEMM_SMEM>>>(
        ahi, alo, owhi, owlo, out_b, out, nullptr, nullptr, MROWS, FDIM, FDIM);
}